// round 5
// baseline (speedup 1.0000x reference)
#include <cuda_runtime.h>
#include <cstdint>

// Problem constants
#define BB 4
#define TT 2048
#define HH 2048
#define DD 4
#define FFN 8192
#define MM (BB * TT)          // 8192 tokens

// Scratch (device globals: allocation-free per harness rules)
__device__ float g_h [MM * HH];     // h (LN1) -> later attin -> later gate
__device__ float g_v [MM * HH];     // v       -> later h2
__device__ float g_k [MM * HH];     // k       -> later km
__device__ float g_r [MM * HH];     // r raw   -> later val
__device__ float g_x1[MM * HH];     // x1
__device__ float g_kk[MM * FFN];    // kk (relu^2)
__device__ float g_lw[MM * DD];     // level softmax weights
__device__ float g_dec[DD * HH];    // decay

// ---------------------------------------------------------------------------
// LayerNorm: one block per row of H=2048
// ---------------------------------------------------------------------------
__global__ __launch_bounds__(256) void ln_kernel(
    const float* __restrict__ x, const float* __restrict__ s,
    const float* __restrict__ bvec, float* __restrict__ out)
{
    const int row = blockIdx.x;
    const float* xr = x + (size_t)row * HH;
    float sum = 0.f, sq = 0.f;
    for (int i = threadIdx.x; i < HH; i += 256) {
        float v = xr[i];
        sum += v;
        sq = fmaf(v, v, sq);
    }
    for (int o = 16; o; o >>= 1) {
        sum += __shfl_down_sync(0xffffffffu, sum, o);
        sq  += __shfl_down_sync(0xffffffffu, sq,  o);
    }
    __shared__ float s1[8], s2[8];
    const int lane = threadIdx.x & 31, w = threadIdx.x >> 5;
    if (!lane) { s1[w] = sum; s2[w] = sq; }
    __syncthreads();
    if (w == 0) {
        sum = (lane < 8) ? s1[lane] : 0.f;
        sq  = (lane < 8) ? s2[lane] : 0.f;
        for (int o = 4; o; o >>= 1) {
            sum += __shfl_down_sync(0xffffffffu, sum, o);
            sq  += __shfl_down_sync(0xffffffffu, sq,  o);
        }
        if (!lane) { s1[0] = sum; s2[0] = sq; }
    }
    __syncthreads();
    const float mean = s1[0] * (1.f / HH);
    const float var  = s2[0] * (1.f / HH) - mean * mean;
    const float inv  = rsqrtf(var + 1e-5f);
    float* orow = out + (size_t)row * HH;
    for (int i = threadIdx.x; i < HH; i += 256)
        orow[i] = (xr[i] - mean) * inv * s[i] + bvec[i];
}

// ---------------------------------------------------------------------------
// Level projection + softmax over D=4: one block per row
// ---------------------------------------------------------------------------
__global__ __launch_bounds__(256) void lvl_kernel(
    const float* __restrict__ h, const float* __restrict__ W,
    const float* __restrict__ bias, float* __restrict__ lw)
{
    const int row = blockIdx.x;
    const float* hr = h + (size_t)row * HH;
    float a0 = 0.f, a1 = 0.f, a2 = 0.f, a3 = 0.f;
    for (int i = threadIdx.x; i < HH; i += 256) {
        const float hv = hr[i];
        const float4 w = *(const float4*)(W + (size_t)i * 4);
        a0 = fmaf(hv, w.x, a0); a1 = fmaf(hv, w.y, a1);
        a2 = fmaf(hv, w.z, a2); a3 = fmaf(hv, w.w, a3);
    }
    for (int o = 16; o; o >>= 1) {
        a0 += __shfl_down_sync(0xffffffffu, a0, o);
        a1 += __shfl_down_sync(0xffffffffu, a1, o);
        a2 += __shfl_down_sync(0xffffffffu, a2, o);
        a3 += __shfl_down_sync(0xffffffffu, a3, o);
    }
    __shared__ float red[8][4];
    const int lane = threadIdx.x & 31, w = threadIdx.x >> 5;
    if (!lane) { red[w][0] = a0; red[w][1] = a1; red[w][2] = a2; red[w][3] = a3; }
    __syncthreads();
    if (threadIdx.x == 0) {
        float s[4];
        for (int d = 0; d < 4; d++) {
            s[d] = bias[d];
            for (int ww = 0; ww < 8; ww++) s[d] += red[ww][d];
        }
        float mx = fmaxf(fmaxf(s[0], s[1]), fmaxf(s[2], s[3]));
        float e[4], tot = 0.f;
        for (int d = 0; d < 4; d++) { e[d] = expf(s[d] - mx); tot += e[d]; }
        const float rinv = 1.f / tot;
        for (int d = 0; d < 4; d++) lw[(size_t)row * 4 + d] = e[d] * rinv;
    }
}

// ---------------------------------------------------------------------------
// decay[d,h] = exp(-exp(td[d,h]))
// ---------------------------------------------------------------------------
__global__ void decay_kernel(const float* __restrict__ td, float* __restrict__ dec)
{
    const int i = blockIdx.x * blockDim.x + threadIdx.x;
    if (i < DD * HH) dec[i] = expf(-expf(td[i]));
}

// ---------------------------------------------------------------------------
// attin = sigmoid(r_raw) * sum_d lw_d * (state[b,d,h]*decay[d,h] + k*v)
// ---------------------------------------------------------------------------
__global__ __launch_bounds__(256) void attn_elem_kernel(
    const float* __restrict__ v, const float* __restrict__ k,
    const float* __restrict__ rraw, const float* __restrict__ lw,
    const float* __restrict__ state, const float* __restrict__ dec,
    float* __restrict__ attin)
{
    const size_t idx = (size_t)blockIdx.x * 256 + threadIdx.x;
    const int col = (int)(idx & (HH - 1));
    const int row = (int)(idx >> 11);           // /HH (2048)
    const int b   = row >> 11;                  // /TT (2048)
    const float kv = k[idx] * v[idx];
    const float r  = 1.f / (1.f + __expf(-rraw[idx]));
    const float* lwr = lw + (size_t)row * 4;
    float w = 0.f;
#pragma unroll
    for (int d = 0; d < DD; d++)
        w += lwr[d] * (state[((size_t)b * DD + d) * HH + col] * dec[d * HH + col] + kv);
    attin[idx] = r * w;
}

// ---------------------------------------------------------------------------
// km = h2*tmk + shift(h2)*(1-tmk), shift(.,0) = cm_state
// ---------------------------------------------------------------------------
__global__ __launch_bounds__(256) void km_kernel(
    const float* __restrict__ h2, const float* __restrict__ cm,
    const float* __restrict__ tmk, float* __restrict__ km)
{
    const size_t idx = (size_t)blockIdx.x * 256 + threadIdx.x;
    const int col = (int)(idx & (HH - 1));
    const int row = (int)(idx >> 11);
    const int t = row & (TT - 1);
    const int b = row >> 11;
    const float prev = (t == 0) ? cm[(size_t)b * HH + col] : h2[idx - HH];
    const float tk = tmk[col];
    km[idx] = h2[idx] * tk + prev * (1.f - tk);
}

// ---------------------------------------------------------------------------
// out = x1 + val * sigmoid(gate)
// ---------------------------------------------------------------------------
__global__ __launch_bounds__(256) void final_kernel(
    const float* __restrict__ x1, const float* __restrict__ val,
    const float* __restrict__ gate, float* __restrict__ out)
{
    const size_t idx = (size_t)blockIdx.x * 256 + threadIdx.x;
    const float g = 1.f / (1.f + __expf(-gate[idx]));
    out[idx] = x1[idx] + val[idx] * g;
}

// ---------------------------------------------------------------------------
// Tiled SGEMM: C[M,N] = A[M,K] @ B[K,N]  (all row-major)
// 128x128 block tile, BK=16, 256 threads, 8x8 microtile, double-buffered smem.
// EPI: 0 = plain store, 1 = C += Res (residual), 2 = relu(C)^2
// Requires M%128==0, N%128==0, K%16==0.
// ---------------------------------------------------------------------------
template <int EPI>
__global__ __launch_bounds__(256) void sgemm_kernel(
    const float* __restrict__ A, const float* __restrict__ B,
    const float* __restrict__ Res, float* __restrict__ C,
    int M, int N, int K)
{
    __shared__ __align__(16) float As[2][16][128];
    __shared__ __align__(16) float Bs[2][16][128];

    const int tid = threadIdx.x;
    const int tx = tid & 15;         // col group
    const int ty = tid >> 4;         // row group
    const int bm = blockIdx.y * 128;
    const int bn = blockIdx.x * 128;

    const int arow = tid >> 2;            // 0..63
    const int acol = (tid & 3) << 2;      // 0,4,8,12
    const int brow = tid >> 5;            // 0..7
    const int bcol = (tid & 31) << 2;     // 0..124

    float acc[8][8];
#pragma unroll
    for (int i = 0; i < 8; i++)
#pragma unroll
        for (int j = 0; j < 8; j++) acc[i][j] = 0.f;

    // preload tile 0
    {
        float4 a0 = *(const float4*)(A + (size_t)(bm + arow) * K + acol);
        float4 a1 = *(const float4*)(A + (size_t)(bm + arow + 64) * K + acol);
        float4 b0 = *(const float4*)(B + (size_t)brow * N + bn + bcol);
        float4 b1 = *(const float4*)(B + (size_t)(brow + 8) * N + bn + bcol);
        As[0][acol + 0][arow] = a0.x; As[0][acol + 1][arow] = a0.y;
        As[0][acol + 2][arow] = a0.z; As[0][acol + 3][arow] = a0.w;
        As[0][acol + 0][arow + 64] = a1.x; As[0][acol + 1][arow + 64] = a1.y;
        As[0][acol + 2][arow + 64] = a1.z; As[0][acol + 3][arow + 64] = a1.w;
        *(float4*)&Bs[0][brow][bcol]     = b0;
        *(float4*)&Bs[0][brow + 8][bcol] = b1;
    }
    __syncthreads();

    const int nt = K >> 4;
    for (int t = 0; t < nt; ++t) {
        const int buf = t & 1;
        float4 a0, a1, b0, b1;
        if (t + 1 < nt) {
            const int k0 = (t + 1) << 4;
            a0 = *(const float4*)(A + (size_t)(bm + arow) * K + k0 + acol);
            a1 = *(const float4*)(A + (size_t)(bm + arow + 64) * K + k0 + acol);
            b0 = *(const float4*)(B + (size_t)(k0 + brow) * N + bn + bcol);
            b1 = *(const float4*)(B + (size_t)(k0 + brow + 8) * N + bn + bcol);
        }
#pragma unroll
        for (int kk = 0; kk < 16; ++kk) {
            const float4 av0 = *(const float4*)&As[buf][kk][ty * 8];
            const float4 av1 = *(const float4*)&As[buf][kk][ty * 8 + 4];
            const float4 bv0 = *(const float4*)&Bs[buf][kk][tx * 8];
            const float4 bv1 = *(const float4*)&Bs[buf][kk][tx * 8 + 4];
            const float a[8] = {av0.x, av0.y, av0.z, av0.w, av1.x, av1.y, av1.z, av1.w};
            const float b[8] = {bv0.x, bv0.y, bv0.z, bv0.w, bv1.x, bv1.y, bv1.z, bv1.w};
#pragma unroll
            for (int i = 0; i < 8; i++)
#pragma unroll
                for (int j = 0; j < 8; j++)
                    acc[i][j] = fmaf(a[i], b[j], acc[i][j]);
        }
        if (t + 1 < nt) {
            const int nb = buf ^ 1;
            As[nb][acol + 0][arow] = a0.x; As[nb][acol + 1][arow] = a0.y;
            As[nb][acol + 2][arow] = a0.z; As[nb][acol + 3][arow] = a0.w;
            As[nb][acol + 0][arow + 64] = a1.x; As[nb][acol + 1][arow + 64] = a1.y;
            As[nb][acol + 2][arow + 64] = a1.z; As[nb][acol + 3][arow + 64] = a1.w;
            *(float4*)&Bs[nb][brow][bcol]     = b0;
            *(float4*)&Bs[nb][brow + 8][bcol] = b1;
        }
        __syncthreads();
    }

    // epilogue
#pragma unroll
    for (int i = 0; i < 8; i++) {
        const int cm = bm + ty * 8 + i;
#pragma unroll
        for (int j = 0; j < 8; j += 4) {
            const int cn = bn + tx * 8 + j;
            float4 o;
            o.x = acc[i][j + 0]; o.y = acc[i][j + 1];
            o.z = acc[i][j + 2]; o.w = acc[i][j + 3];
            if (EPI == 1) {
                const float4 rv = *(const float4*)(Res + (size_t)cm * N + cn);
                o.x += rv.x; o.y += rv.y; o.z += rv.z; o.w += rv.w;
            }
            if (EPI == 2) {
                o.x = fmaxf(o.x, 0.f); o.x *= o.x;
                o.y = fmaxf(o.y, 0.f); o.y *= o.y;
                o.z = fmaxf(o.z, 0.f); o.z *= o.z;
                o.w = fmaxf(o.w, 0.f); o.w *= o.w;
            }
            *(float4*)(C + (size_t)cm * N + cn) = o;
        }
    }
}

// ---------------------------------------------------------------------------
extern "C" void kernel_launch(void* const* d_in, const int* in_sizes, int n_in,
                              void* d_out, int out_size)
{
    const float* x       = (const float*)d_in[0];
    const float* att_st  = (const float*)d_in[1];
    const float* cm_st   = (const float*)d_in[2];
    const float* ln1_s   = (const float*)d_in[3];
    const float* ln1_b   = (const float*)d_in[4];
    const float* ln2_s   = (const float*)d_in[5];
    const float* ln2_b   = (const float*)d_in[6];
    const float* td      = (const float*)d_in[7];
    const float* lvl_w   = (const float*)d_in[8];
    const float* lvl_b   = (const float*)d_in[9];
    const float* Wv      = (const float*)d_in[10];
    const float* Wk      = (const float*)d_in[11];
    const float* Wr      = (const float*)d_in[12];
    const float* Wo      = (const float*)d_in[13];
    const float* tmk     = (const float*)d_in[14];
    const float* Wkey    = (const float*)d_in[15];
    const float* Wval    = (const float*)d_in[16];
    const float* Wgate   = (const float*)d_in[17];
    float* out = (float*)d_out;

    float *h, *v, *k, *r, *x1, *kk, *lw, *dec;
    cudaGetSymbolAddress((void**)&h,   g_h);
    cudaGetSymbolAddress((void**)&v,   g_v);
    cudaGetSymbolAddress((void**)&k,   g_k);
    cudaGetSymbolAddress((void**)&r,   g_r);
    cudaGetSymbolAddress((void**)&x1,  g_x1);
    cudaGetSymbolAddress((void**)&kk,  g_kk);
    cudaGetSymbolAddress((void**)&lw,  g_lw);
    cudaGetSymbolAddress((void**)&dec, g_dec);

    const dim3 gemmB(256);
    const dim3 gHH(HH / 128, MM / 128);     // N=2048
    const dim3 gFF(FFN / 128, MM / 128);    // N=8192
    const int ELEM_BLKS = (MM * HH) / 256;

    // --- attention half ---
    ln_kernel<<<MM, 256>>>(x, ln1_s, ln1_b, h);
    sgemm_kernel<0><<<gHH, gemmB>>>(h, Wv, nullptr, v, MM, HH, HH);
    sgemm_kernel<0><<<gHH, gemmB>>>(h, Wk, nullptr, k, MM, HH, HH);
    sgemm_kernel<0><<<gHH, gemmB>>>(h, Wr, nullptr, r, MM, HH, HH);
    lvl_kernel<<<MM, 256>>>(h, lvl_w, lvl_b, lw);
    decay_kernel<<<(DD * HH + 255) / 256, 256>>>(td, dec);
    attn_elem_kernel<<<ELEM_BLKS, 256>>>(v, k, r, lw, att_st, dec, h);  // attin -> h
    sgemm_kernel<1><<<gHH, gemmB>>>(h, Wo, x, x1, MM, HH, HH);          // x1 = x + att

    // --- channel-mix half ---
    ln_kernel<<<MM, 256>>>(x1, ln2_s, ln2_b, v);                        // h2 -> v
    km_kernel<<<ELEM_BLKS, 256>>>(v, cm_st, tmk, k);                    // km -> k
    sgemm_kernel<2><<<gFF, gemmB>>>(k, Wkey, nullptr, kk, MM, FFN, HH); // kk = relu(km@Wkey)^2
    sgemm_kernel<0><<<gHH, gemmB>>>(kk, Wval,  nullptr, r, MM, HH, FFN); // val  -> r
    sgemm_kernel<0><<<gHH, gemmB>>>(kk, Wgate, nullptr, h, MM, HH, FFN); // gate -> h
    final_kernel<<<ELEM_BLKS, 256>>>(x1, r, h, out);
}

// round 7
// speedup vs baseline: 4.8929x; 4.8929x over previous
#include <cuda_runtime.h>
#include <cstdint>

// Problem constants
#define BB 4
#define TT 2048
#define HH 2048
#define DD 4
#define FFN 8192
#define MM (BB * TT)          // 8192 tokens

// Scratch (device globals: allocation-free per harness rules)
__device__ float g_h [MM * HH];     // h (LN1) -> later attin -> later gate
__device__ float g_v [MM * HH];     // v       -> later h2
__device__ float g_k [MM * HH];     // k       -> later km
__device__ float g_r [MM * HH];     // r raw   -> later val
__device__ float g_x1[MM * HH];     // x1
__device__ float g_kk[MM * FFN];    // kk (relu^2)
__device__ float g_lw[MM * DD];     // level softmax weights
__device__ float g_dec[DD * HH];    // decay
// Transposed weights ([N,K] row-major for mma.sync row.col B operand)
__device__ float g_WvT  [HH * HH];
__device__ float g_WkT  [HH * HH];
__device__ float g_WrT  [HH * HH];
__device__ float g_WoT  [HH * HH];
__device__ float g_WkeyT[FFN * HH];
__device__ float g_WvalT[HH * FFN];
__device__ float g_WgateT[HH * FFN];

// ---------------------------------------------------------------------------
__device__ __forceinline__ uint32_t f2tf(float f) {
    uint32_t r;
    asm("cvt.rna.tf32.f32 %0, %1;" : "=r"(r) : "f"(f));
    return r;
}

__device__ __forceinline__ void mma_tf32(float c[4], const uint32_t a[4], const uint32_t b[2]) {
    asm volatile(
        "mma.sync.aligned.m16n8k8.row.col.f32.tf32.tf32.f32 "
        "{%0,%1,%2,%3}, {%4,%5,%6,%7}, {%8,%9}, {%0,%1,%2,%3};"
        : "+f"(c[0]), "+f"(c[1]), "+f"(c[2]), "+f"(c[3])
        : "r"(a[0]), "r"(a[1]), "r"(a[2]), "r"(a[3]), "r"(b[0]), "r"(b[1]));
}

// ===========================================================================
// Tensor-core tf32 GEMM: C[M,N] = A[M,K] @ Bt[N,K]^T   (Bt row-major [N,K])
// Block tile 128x128, BK=16, 256 threads (8 warps = 2x4), warp tile 64x32,
// double-buffered SMEM. EPI: 0 plain, 1 +Res, 2 relu(.)^2
// Requires M%128==0, N%128==0, K%16==0.
// ===========================================================================
template <int EPI>
__global__ __launch_bounds__(256, 2) void mma_gemm_kernel(
    const float* __restrict__ A, const float* __restrict__ Bt,
    const float* __restrict__ Res, float* __restrict__ C,
    int M, int N, int K)
{
    __shared__ uint32_t As[2][128][20];   // [buf][m][k], pad 16->20
    __shared__ uint32_t Bs[2][128][20];   // [buf][n][k]

    const int tid = threadIdx.x;
    const int wid = tid >> 5, lane = tid & 31;
    const int wm = wid & 1, wn = wid >> 1;        // 2(m) x 4(n) warp grid
    const int group = lane >> 2, tg = lane & 3;   // mma fragment coords
    const int bm = blockIdx.y * 128, bn = blockIdx.x * 128;

    const int lr = tid >> 2;          // 0..63
    const int lc = (tid & 3) << 2;    // 0,4,8,12

    float c[4][4][4];
#pragma unroll
    for (int mi = 0; mi < 4; mi++)
#pragma unroll
        for (int ni = 0; ni < 4; ni++)
#pragma unroll
            for (int j = 0; j < 4; j++) c[mi][ni][j] = 0.f;

    const float* Arow0 = A  + (size_t)(bm + lr) * K + lc;
    const float* Arow1 = A  + (size_t)(bm + lr + 64) * K + lc;
    const float* Brow0 = Bt + (size_t)(bn + lr) * K + lc;
    const float* Brow1 = Bt + (size_t)(bn + lr + 64) * K + lc;

    // preload tile 0
    {
        const float4 a0 = *(const float4*)(Arow0);
        const float4 a1 = *(const float4*)(Arow1);
        const float4 b0 = *(const float4*)(Brow0);
        const float4 b1 = *(const float4*)(Brow1);
        *(uint4*)&As[0][lr][lc]      = make_uint4(f2tf(a0.x), f2tf(a0.y), f2tf(a0.z), f2tf(a0.w));
        *(uint4*)&As[0][lr + 64][lc] = make_uint4(f2tf(a1.x), f2tf(a1.y), f2tf(a1.z), f2tf(a1.w));
        *(uint4*)&Bs[0][lr][lc]      = make_uint4(f2tf(b0.x), f2tf(b0.y), f2tf(b0.z), f2tf(b0.w));
        *(uint4*)&Bs[0][lr + 64][lc] = make_uint4(f2tf(b1.x), f2tf(b1.y), f2tf(b1.z), f2tf(b1.w));
    }
    __syncthreads();

    const int nt = K >> 4;
    for (int t = 0; t < nt; ++t) {
        const int buf = t & 1;
        float4 a0, a1, b0, b1;
        if (t + 1 < nt) {
            const int k0 = (t + 1) << 4;
            a0 = *(const float4*)(Arow0 + k0);
            a1 = *(const float4*)(Arow1 + k0);
            b0 = *(const float4*)(Brow0 + k0);
            b1 = *(const float4*)(Brow1 + k0);
        }
#pragma unroll
        for (int ks = 0; ks < 2; ++ks) {
            const int k0 = ks * 8;
            uint32_t af[4][4], bf[4][2];
#pragma unroll
            for (int mi = 0; mi < 4; mi++) {
                const int rb = wm * 64 + mi * 16;
                af[mi][0] = As[buf][rb + group][k0 + tg];
                af[mi][1] = As[buf][rb + group + 8][k0 + tg];
                af[mi][2] = As[buf][rb + group][k0 + tg + 4];
                af[mi][3] = As[buf][rb + group + 8][k0 + tg + 4];
            }
#pragma unroll
            for (int ni = 0; ni < 4; ni++) {
                const int nb = wn * 32 + ni * 8;
                bf[ni][0] = Bs[buf][nb + group][k0 + tg];
                bf[ni][1] = Bs[buf][nb + group][k0 + tg + 4];
            }
#pragma unroll
            for (int mi = 0; mi < 4; mi++)
#pragma unroll
                for (int ni = 0; ni < 4; ni++)
                    mma_tf32(c[mi][ni], af[mi], bf[ni]);
        }
        if (t + 1 < nt) {
            const int nb = buf ^ 1;
            *(uint4*)&As[nb][lr][lc]      = make_uint4(f2tf(a0.x), f2tf(a0.y), f2tf(a0.z), f2tf(a0.w));
            *(uint4*)&As[nb][lr + 64][lc] = make_uint4(f2tf(a1.x), f2tf(a1.y), f2tf(a1.z), f2tf(a1.w));
            *(uint4*)&Bs[nb][lr][lc]      = make_uint4(f2tf(b0.x), f2tf(b0.y), f2tf(b0.z), f2tf(b0.w));
            *(uint4*)&Bs[nb][lr + 64][lc] = make_uint4(f2tf(b1.x), f2tf(b1.y), f2tf(b1.z), f2tf(b1.w));
        }
        __syncthreads();
    }

    // epilogue: c0,c1 -> (m0, n0..n0+1); c2,c3 -> (m0+8, n0..n0+1)
#pragma unroll
    for (int mi = 0; mi < 4; mi++) {
        const int m0 = bm + wm * 64 + mi * 16 + group;
#pragma unroll
        for (int ni = 0; ni < 4; ni++) {
            const int n0 = bn + wn * 32 + ni * 8 + tg * 2;
            float2 lo = make_float2(c[mi][ni][0], c[mi][ni][1]);
            float2 hi = make_float2(c[mi][ni][2], c[mi][ni][3]);
            if (EPI == 1) {
                const float2 r0 = *(const float2*)(Res + (size_t)m0 * N + n0);
                const float2 r1 = *(const float2*)(Res + (size_t)(m0 + 8) * N + n0);
                lo.x += r0.x; lo.y += r0.y; hi.x += r1.x; hi.y += r1.y;
            }
            if (EPI == 2) {
                lo.x = fmaxf(lo.x, 0.f); lo.x *= lo.x;
                lo.y = fmaxf(lo.y, 0.f); lo.y *= lo.y;
                hi.x = fmaxf(hi.x, 0.f); hi.x *= hi.x;
                hi.y = fmaxf(hi.y, 0.f); hi.y *= hi.y;
            }
            *(float2*)(C + (size_t)m0 * N + n0) = lo;
            *(float2*)(C + (size_t)(m0 + 8) * N + n0) = hi;
        }
    }
}

// ---------------------------------------------------------------------------
// Transpose: in[R,C] -> out[C,R]  (R,C multiples of 32)
// ---------------------------------------------------------------------------
__global__ __launch_bounds__(256) void transpose_kernel(
    const float* __restrict__ in, float* __restrict__ out, int R, int C)
{
    __shared__ float tile[32][33];
    const int c0 = blockIdx.x * 32, r0 = blockIdx.y * 32;
    for (int i = threadIdx.y; i < 32; i += 8)
        tile[i][threadIdx.x] = in[(size_t)(r0 + i) * C + c0 + threadIdx.x];
    __syncthreads();
    for (int i = threadIdx.y; i < 32; i += 8)
        out[(size_t)(c0 + i) * R + r0 + threadIdx.x] = tile[threadIdx.x][i];
}

// ---------------------------------------------------------------------------
// LayerNorm: one block per row of H=2048
// ---------------------------------------------------------------------------
__global__ __launch_bounds__(256) void ln_kernel(
    const float* __restrict__ x, const float* __restrict__ s,
    const float* __restrict__ bvec, float* __restrict__ out)
{
    const int row = blockIdx.x;
    const float* xr = x + (size_t)row * HH;
    float sum = 0.f, sq = 0.f;
    for (int i = threadIdx.x; i < HH; i += 256) {
        float v = xr[i];
        sum += v;
        sq = fmaf(v, v, sq);
    }
    for (int o = 16; o; o >>= 1) {
        sum += __shfl_down_sync(0xffffffffu, sum, o);
        sq  += __shfl_down_sync(0xffffffffu, sq,  o);
    }
    __shared__ float s1[8], s2[8];
    const int lane = threadIdx.x & 31, w = threadIdx.x >> 5;
    if (!lane) { s1[w] = sum; s2[w] = sq; }
    __syncthreads();
    if (w == 0) {
        sum = (lane < 8) ? s1[lane] : 0.f;
        sq  = (lane < 8) ? s2[lane] : 0.f;
        for (int o = 4; o; o >>= 1) {
            sum += __shfl_down_sync(0xffffffffu, sum, o);
            sq  += __shfl_down_sync(0xffffffffu, sq,  o);
        }
        if (!lane) { s1[0] = sum; s2[0] = sq; }
    }
    __syncthreads();
    const float mean = s1[0] * (1.f / HH);
    const float var  = s2[0] * (1.f / HH) - mean * mean;
    const float inv  = rsqrtf(var + 1e-5f);
    float* orow = out + (size_t)row * HH;
    for (int i = threadIdx.x; i < HH; i += 256)
        orow[i] = (xr[i] - mean) * inv * s[i] + bvec[i];
}

// ---------------------------------------------------------------------------
// Level projection + softmax over D=4: one block per row
// ---------------------------------------------------------------------------
__global__ __launch_bounds__(256) void lvl_kernel(
    const float* __restrict__ h, const float* __restrict__ W,
    const float* __restrict__ bias, float* __restrict__ lw)
{
    const int row = blockIdx.x;
    const float* hr = h + (size_t)row * HH;
    float a0 = 0.f, a1 = 0.f, a2 = 0.f, a3 = 0.f;
    for (int i = threadIdx.x; i < HH; i += 256) {
        const float hv = hr[i];
        const float4 w = *(const float4*)(W + (size_t)i * 4);
        a0 = fmaf(hv, w.x, a0); a1 = fmaf(hv, w.y, a1);
        a2 = fmaf(hv, w.z, a2); a3 = fmaf(hv, w.w, a3);
    }
    for (int o = 16; o; o >>= 1) {
        a0 += __shfl_down_sync(0xffffffffu, a0, o);
        a1 += __shfl_down_sync(0xffffffffu, a1, o);
        a2 += __shfl_down_sync(0xffffffffu, a2, o);
        a3 += __shfl_down_sync(0xffffffffu, a3, o);
    }
    __shared__ float red[8][4];
    const int lane = threadIdx.x & 31, w = threadIdx.x >> 5;
    if (!lane) { red[w][0] = a0; red[w][1] = a1; red[w][2] = a2; red[w][3] = a3; }
    __syncthreads();
    if (threadIdx.x == 0) {
        float s[4];
        for (int d = 0; d < 4; d++) {
            s[d] = bias[d];
            for (int ww = 0; ww < 8; ww++) s[d] += red[ww][d];
        }
        float mx = fmaxf(fmaxf(s[0], s[1]), fmaxf(s[2], s[3]));
        float e[4], tot = 0.f;
        for (int d = 0; d < 4; d++) { e[d] = expf(s[d] - mx); tot += e[d]; }
        const float rinv = 1.f / tot;
        for (int d = 0; d < 4; d++) lw[(size_t)row * 4 + d] = e[d] * rinv;
    }
}

__global__ void decay_kernel(const float* __restrict__ td, float* __restrict__ dec)
{
    const int i = blockIdx.x * blockDim.x + threadIdx.x;
    if (i < DD * HH) dec[i] = expf(-expf(td[i]));
}

__global__ __launch_bounds__(256) void attn_elem_kernel(
    const float* __restrict__ v, const float* __restrict__ k,
    const float* __restrict__ rraw, const float* __restrict__ lw,
    const float* __restrict__ state, const float* __restrict__ dec,
    float* __restrict__ attin)
{
    const size_t idx = (size_t)blockIdx.x * 256 + threadIdx.x;
    const int col = (int)(idx & (HH - 1));
    const int row = (int)(idx >> 11);
    const int b   = row >> 11;
    const float kv = k[idx] * v[idx];
    const float r  = 1.f / (1.f + __expf(-rraw[idx]));
    const float* lwr = lw + (size_t)row * 4;
    float w = 0.f;
#pragma unroll
    for (int d = 0; d < DD; d++)
        w += lwr[d] * (state[((size_t)b * DD + d) * HH + col] * dec[d * HH + col] + kv);
    attin[idx] = r * w;
}

__global__ __launch_bounds__(256) void km_kernel(
    const float* __restrict__ h2, const float* __restrict__ cm,
    const float* __restrict__ tmk, float* __restrict__ km)
{
    const size_t idx = (size_t)blockIdx.x * 256 + threadIdx.x;
    const int col = (int)(idx & (HH - 1));
    const int row = (int)(idx >> 11);
    const int t = row & (TT - 1);
    const int b = row >> 11;
    const float prev = (t == 0) ? cm[(size_t)b * HH + col] : h2[idx - HH];
    const float tk = tmk[col];
    km[idx] = h2[idx] * tk + prev * (1.f - tk);
}

__global__ __launch_bounds__(256) void final_kernel(
    const float* __restrict__ x1, const float* __restrict__ val,
    const float* __restrict__ gate, float* __restrict__ out)
{
    const size_t idx = (size_t)blockIdx.x * 256 + threadIdx.x;
    const float g = 1.f / (1.f + __expf(-gate[idx]));
    out[idx] = x1[idx] + val[idx] * g;
}

// ---------------------------------------------------------------------------
extern "C" void kernel_launch(void* const* d_in, const int* in_sizes, int n_in,
                              void* d_out, int out_size)
{
    const float* x       = (const float*)d_in[0];
    const float* att_st  = (const float*)d_in[1];
    const float* cm_st   = (const float*)d_in[2];
    const float* ln1_s   = (const float*)d_in[3];
    const float* ln1_b   = (const float*)d_in[4];
    const float* ln2_s   = (const float*)d_in[5];
    const float* ln2_b   = (const float*)d_in[6];
    const float* td      = (const float*)d_in[7];
    const float* lvl_w   = (const float*)d_in[8];
    const float* lvl_b   = (const float*)d_in[9];
    const float* Wv      = (const float*)d_in[10];
    const float* Wk      = (const float*)d_in[11];
    const float* Wr      = (const float*)d_in[12];
    const float* Wo      = (const float*)d_in[13];
    const float* tmk     = (const float*)d_in[14];
    const float* Wkey    = (const float*)d_in[15];
    const float* Wval    = (const float*)d_in[16];
    const float* Wgate   = (const float*)d_in[17];
    float* out = (float*)d_out;

    float *h, *v, *k, *r, *x1, *kk, *lw, *dec;
    float *WvT, *WkT, *WrT, *WoT, *WkeyT, *WvalT, *WgateT;
    cudaGetSymbolAddress((void**)&h,   g_h);
    cudaGetSymbolAddress((void**)&v,   g_v);
    cudaGetSymbolAddress((void**)&k,   g_k);
    cudaGetSymbolAddress((void**)&r,   g_r);
    cudaGetSymbolAddress((void**)&x1,  g_x1);
    cudaGetSymbolAddress((void**)&kk,  g_kk);
    cudaGetSymbolAddress((void**)&lw,  g_lw);
    cudaGetSymbolAddress((void**)&dec, g_dec);
    cudaGetSymbolAddress((void**)&WvT,   g_WvT);
    cudaGetSymbolAddress((void**)&WkT,   g_WkT);
    cudaGetSymbolAddress((void**)&WrT,   g_WrT);
    cudaGetSymbolAddress((void**)&WoT,   g_WoT);
    cudaGetSymbolAddress((void**)&WkeyT, g_WkeyT);
    cudaGetSymbolAddress((void**)&WvalT, g_WvalT);
    cudaGetSymbolAddress((void**)&WgateT,g_WgateT);

    const dim3 tb(32, 8);
    // weight transposes: out[N,K] = in[K,N]^T ; grid (C/32, R/32) over in[R,C]
    transpose_kernel<<<dim3(HH/32,  HH/32),  tb>>>(Wv,    WvT,    HH,  HH);
    transpose_kernel<<<dim3(HH/32,  HH/32),  tb>>>(Wk,    WkT,    HH,  HH);
    transpose_kernel<<<dim3(HH/32,  HH/32),  tb>>>(Wr,    WrT,    HH,  HH);
    transpose_kernel<<<dim3(HH/32,  HH/32),  tb>>>(Wo,    WoT,    HH,  HH);
    transpose_kernel<<<dim3(FFN/32, HH/32),  tb>>>(Wkey,  WkeyT,  HH,  FFN);
    transpose_kernel<<<dim3(HH/32,  FFN/32), tb>>>(Wval,  WvalT,  FFN, HH);
    transpose_kernel<<<dim3(HH/32,  FFN/32), tb>>>(Wgate, WgateT, FFN, HH);

    const dim3 gHH(HH / 128, MM / 128);     // N=2048: (16, 64)
    const dim3 gFF(FFN / 128, MM / 128);    // N=8192: (64, 64)
    const int ELEM_BLKS = (MM * HH) / 256;

    // --- attention half ---
    ln_kernel<<<MM, 256>>>(x, ln1_s, ln1_b, h);
    mma_gemm_kernel<0><<<gHH, 256>>>(h, WvT, nullptr, v, MM, HH, HH);
    mma_gemm_kernel<0><<<gHH, 256>>>(h, WkT, nullptr, k, MM, HH, HH);
    mma_gemm_kernel<0><<<gHH, 256>>>(h, WrT, nullptr, r, MM, HH, HH);
    lvl_kernel<<<MM, 256>>>(h, lvl_w, lvl_b, lw);
    decay_kernel<<<(DD * HH + 255) / 256, 256>>>(td, dec);
    attn_elem_kernel<<<ELEM_BLKS, 256>>>(v, k, r, lw, att_st, dec, h);   // attin -> h
    mma_gemm_kernel<1><<<gHH, 256>>>(h, WoT, x, x1, MM, HH, HH);

    // --- channel-mix half ---
    ln_kernel<<<MM, 256>>>(x1, ln2_s, ln2_b, v);                          // h2 -> v
    km_kernel<<<ELEM_BLKS, 256>>>(v, cm_st, tmk, k);                      // km -> k
    mma_gemm_kernel<2><<<gFF, 256>>>(k, WkeyT, nullptr, kk, MM, FFN, HH);
    mma_gemm_kernel<0><<<gHH, 256>>>(kk, WvalT,  nullptr, r, MM, HH, FFN);
    mma_gemm_kernel<0><<<gHH, 256>>>(kk, WgateT, nullptr, h, MM, HH, FFN);
    final_kernel<<<ELEM_BLKS, 256>>>(x1, r, h, out);
}

// round 8
// speedup vs baseline: 5.2129x; 1.0654x over previous
#include <cuda_runtime.h>
#include <cuda_fp16.h>
#include <cstdint>

// Problem constants
#define BB 4
#define TT 2048
#define HH 2048
#define DD 4
#define FFN 8192
#define MM (BB * TT)          // 8192 tokens

// Scratch (device globals: allocation-free per harness rules)
__device__ float g_h [MM * HH];     // h (LN1) -> later attin -> later gate
__device__ float g_v [MM * HH];     // v       -> later h2
__device__ float g_k [MM * HH];     // k       -> later km
__device__ float g_r [MM * HH];     // r raw   -> later val
__device__ float g_x1[MM * HH];     // x1
__device__ float g_kk[MM * FFN];    // kk (relu^2)
__device__ float g_lw[MM * DD];     // level softmax weights
__device__ float g_dec[DD * HH];    // decay
// Transposed weights ([N,K] row-major for mma.sync row.col B operand)
__device__ float g_WvT  [HH * HH];
__device__ float g_WkT  [HH * HH];
__device__ float g_WrT  [HH * HH];
__device__ float g_WoT  [HH * HH];
__device__ float g_WkeyT[FFN * HH];
__device__ float g_WvalT[HH * FFN];
__device__ float g_WgateT[HH * FFN];

// ---------------------------------------------------------------------------
__device__ __forceinline__ uint32_t pack_h2(float x, float y) {
    const __half2 h = __floats2half2_rn(x, y);   // x -> low, y -> high
    return *(const uint32_t*)&h;
}

__device__ __forceinline__ void mma_f16(float c[4], const uint32_t a[4], const uint32_t b[2]) {
    asm volatile(
        "mma.sync.aligned.m16n8k16.row.col.f32.f16.f16.f32 "
        "{%0,%1,%2,%3}, {%4,%5,%6,%7}, {%8,%9}, {%0,%1,%2,%3};"
        : "+f"(c[0]), "+f"(c[1]), "+f"(c[2]), "+f"(c[3])
        : "r"(a[0]), "r"(a[1]), "r"(a[2]), "r"(a[3]), "r"(b[0]), "r"(b[1]));
}

// ===========================================================================
// Tensor-core fp16 GEMM (fp32 accum): C[M,N] = A[M,K] @ Bt[N,K]^T
// Block tile 128x128, BK=32, 256 threads (8 warps = 2x4), warp tile 64x32,
// double-buffered SMEM (uint = 2 halfs, row stride 20 uints: conflict-free).
// EPI: 0 plain, 1 +Res, 2 relu(.)^2.  Requires M%128==0, N%128==0, K%32==0.
// ===========================================================================
template <int EPI>
__global__ __launch_bounds__(256, 2) void mma_gemm_kernel(
    const float* __restrict__ A, const float* __restrict__ Bt,
    const float* __restrict__ Res, float* __restrict__ C,
    int M, int N, int K)
{
    __shared__ uint32_t As[2][128][20];   // [buf][m][k-pair], 16 used + 4 pad
    __shared__ uint32_t Bs[2][128][20];   // [buf][n][k-pair]

    const int tid = threadIdx.x;
    const int wid = tid >> 5, lane = tid & 31;
    const int wm = wid & 1, wn = wid >> 1;        // 2(m) x 4(n) warp grid
    const int group = lane >> 2, tg = lane & 3;   // mma fragment coords
    const int bm = blockIdx.y * 128, bn = blockIdx.x * 128;

    // loader coords: 2 threads per row, 16 floats (4 float4) each
    const int lr = tid >> 1;            // 0..127
    const int lc = (tid & 1) << 4;      // 0 or 16 (float col base)

    const float* Arow = A  + (size_t)(bm + lr) * K + lc;
    const float* Brow = Bt + (size_t)(bn + lr) * K + lc;

    float c[4][4][4];
#pragma unroll
    for (int mi = 0; mi < 4; mi++)
#pragma unroll
        for (int ni = 0; ni < 4; ni++)
#pragma unroll
            for (int j = 0; j < 4; j++) c[mi][ni][j] = 0.f;

    auto load_tiles = [&](int k0, int buf) {
#pragma unroll
        for (int q = 0; q < 4; q++) {
            const float4 va = *(const float4*)(Arow + k0 + q * 4);
            const float4 vb = *(const float4*)(Brow + k0 + q * 4);
            const int uc = (lc >> 1) + q * 2;
            As[buf][lr][uc]     = pack_h2(va.x, va.y);
            As[buf][lr][uc + 1] = pack_h2(va.z, va.w);
            Bs[buf][lr][uc]     = pack_h2(vb.x, vb.y);
            Bs[buf][lr][uc + 1] = pack_h2(vb.z, vb.w);
        }
    };

    load_tiles(0, 0);
    __syncthreads();

    const int nt = K >> 5;
    for (int t = 0; t < nt; ++t) {
        const int buf = t & 1;
        if (t + 1 < nt) load_tiles((t + 1) << 5, buf ^ 1);   // fill other buffer
#pragma unroll
        for (int ks = 0; ks < 2; ++ks) {
            const int k0 = ks * 8;                            // uint col base (k16 block)
            uint32_t af[4][4], bf[4][2];
#pragma unroll
            for (int mi = 0; mi < 4; mi++) {
                const int rb = wm * 64 + mi * 16;
                af[mi][0] = As[buf][rb + group][k0 + tg];
                af[mi][1] = As[buf][rb + group + 8][k0 + tg];
                af[mi][2] = As[buf][rb + group][k0 + tg + 4];
                af[mi][3] = As[buf][rb + group + 8][k0 + tg + 4];
            }
#pragma unroll
            for (int ni = 0; ni < 4; ni++) {
                const int nb = wn * 32 + ni * 8;
                bf[ni][0] = Bs[buf][nb + group][k0 + tg];
                bf[ni][1] = Bs[buf][nb + group][k0 + tg + 4];
            }
#pragma unroll
            for (int mi = 0; mi < 4; mi++)
#pragma unroll
                for (int ni = 0; ni < 4; ni++)
                    mma_f16(c[mi][ni], af[mi], bf[ni]);
        }
        __syncthreads();
    }

    // epilogue: c0,c1 -> (m0, n0..n0+1); c2,c3 -> (m0+8, n0..n0+1)
#pragma unroll
    for (int mi = 0; mi < 4; mi++) {
        const int m0 = bm + wm * 64 + mi * 16 + group;
#pragma unroll
        for (int ni = 0; ni < 4; ni++) {
            const int n0 = bn + wn * 32 + ni * 8 + tg * 2;
            float2 lo = make_float2(c[mi][ni][0], c[mi][ni][1]);
            float2 hi = make_float2(c[mi][ni][2], c[mi][ni][3]);
            if (EPI == 1) {
                const float2 r0 = *(const float2*)(Res + (size_t)m0 * N + n0);
                const float2 r1 = *(const float2*)(Res + (size_t)(m0 + 8) * N + n0);
                lo.x += r0.x; lo.y += r0.y; hi.x += r1.x; hi.y += r1.y;
            }
            if (EPI == 2) {
                lo.x = fmaxf(lo.x, 0.f); lo.x *= lo.x;
                lo.y = fmaxf(lo.y, 0.f); lo.y *= lo.y;
                hi.x = fmaxf(hi.x, 0.f); hi.x *= hi.x;
                hi.y = fmaxf(hi.y, 0.f); hi.y *= hi.y;
            }
            *(float2*)(C + (size_t)m0 * N + n0) = lo;
            *(float2*)(C + (size_t)(m0 + 8) * N + n0) = hi;
        }
    }
}

// ---------------------------------------------------------------------------
// Transpose: in[R,C] -> out[C,R]  (R,C multiples of 32)
// ---------------------------------------------------------------------------
__global__ __launch_bounds__(256) void transpose_kernel(
    const float* __restrict__ in, float* __restrict__ out, int R, int C)
{
    __shared__ float tile[32][33];
    const int c0 = blockIdx.x * 32, r0 = blockIdx.y * 32;
    for (int i = threadIdx.y; i < 32; i += 8)
        tile[i][threadIdx.x] = in[(size_t)(r0 + i) * C + c0 + threadIdx.x];
    __syncthreads();
    for (int i = threadIdx.y; i < 32; i += 8)
        out[(size_t)(c0 + i) * R + r0 + threadIdx.x] = tile[threadIdx.x][i];
}

// ---------------------------------------------------------------------------
// LayerNorm: one block per row of H=2048
// ---------------------------------------------------------------------------
__global__ __launch_bounds__(256) void ln_kernel(
    const float* __restrict__ x, const float* __restrict__ s,
    const float* __restrict__ bvec, float* __restrict__ out)
{
    const int row = blockIdx.x;
    const float* xr = x + (size_t)row * HH;
    float sum = 0.f, sq = 0.f;
    for (int i = threadIdx.x; i < HH; i += 256) {
        float v = xr[i];
        sum += v;
        sq = fmaf(v, v, sq);
    }
    for (int o = 16; o; o >>= 1) {
        sum += __shfl_down_sync(0xffffffffu, sum, o);
        sq  += __shfl_down_sync(0xffffffffu, sq,  o);
    }
    __shared__ float s1[8], s2[8];
    const int lane = threadIdx.x & 31, w = threadIdx.x >> 5;
    if (!lane) { s1[w] = sum; s2[w] = sq; }
    __syncthreads();
    if (w == 0) {
        sum = (lane < 8) ? s1[lane] : 0.f;
        sq  = (lane < 8) ? s2[lane] : 0.f;
        for (int o = 4; o; o >>= 1) {
            sum += __shfl_down_sync(0xffffffffu, sum, o);
            sq  += __shfl_down_sync(0xffffffffu, sq,  o);
        }
        if (!lane) { s1[0] = sum; s2[0] = sq; }
    }
    __syncthreads();
    const float mean = s1[0] * (1.f / HH);
    const float var  = s2[0] * (1.f / HH) - mean * mean;
    const float inv  = rsqrtf(var + 1e-5f);
    float* orow = out + (size_t)row * HH;
    for (int i = threadIdx.x; i < HH; i += 256)
        orow[i] = (xr[i] - mean) * inv * s[i] + bvec[i];
}

// ---------------------------------------------------------------------------
// Level projection + softmax over D=4: one block per row
// ---------------------------------------------------------------------------
__global__ __launch_bounds__(256) void lvl_kernel(
    const float* __restrict__ h, const float* __restrict__ W,
    const float* __restrict__ bias, float* __restrict__ lw)
{
    const int row = blockIdx.x;
    const float* hr = h + (size_t)row * HH;
    float a0 = 0.f, a1 = 0.f, a2 = 0.f, a3 = 0.f;
    for (int i = threadIdx.x; i < HH; i += 256) {
        const float hv = hr[i];
        const float4 w = *(const float4*)(W + (size_t)i * 4);
        a0 = fmaf(hv, w.x, a0); a1 = fmaf(hv, w.y, a1);
        a2 = fmaf(hv, w.z, a2); a3 = fmaf(hv, w.w, a3);
    }
    for (int o = 16; o; o >>= 1) {
        a0 += __shfl_down_sync(0xffffffffu, a0, o);
        a1 += __shfl_down_sync(0xffffffffu, a1, o);
        a2 += __shfl_down_sync(0xffffffffu, a2, o);
        a3 += __shfl_down_sync(0xffffffffu, a3, o);
    }
    __shared__ float red[8][4];
    const int lane = threadIdx.x & 31, w = threadIdx.x >> 5;
    if (!lane) { red[w][0] = a0; red[w][1] = a1; red[w][2] = a2; red[w][3] = a3; }
    __syncthreads();
    if (threadIdx.x == 0) {
        float s[4];
        for (int d = 0; d < 4; d++) {
            s[d] = bias[d];
            for (int ww = 0; ww < 8; ww++) s[d] += red[ww][d];
        }
        float mx = fmaxf(fmaxf(s[0], s[1]), fmaxf(s[2], s[3]));
        float e[4], tot = 0.f;
        for (int d = 0; d < 4; d++) { e[d] = expf(s[d] - mx); tot += e[d]; }
        const float rinv = 1.f / tot;
        for (int d = 0; d < 4; d++) lw[(size_t)row * 4 + d] = e[d] * rinv;
    }
}

__global__ void decay_kernel(const float* __restrict__ td, float* __restrict__ dec)
{
    const int i = blockIdx.x * blockDim.x + threadIdx.x;
    if (i < DD * HH) dec[i] = expf(-expf(td[i]));
}

__global__ __launch_bounds__(256) void attn_elem_kernel(
    const float* __restrict__ v, const float* __restrict__ k,
    const float* __restrict__ rraw, const float* __restrict__ lw,
    const float* __restrict__ state, const float* __restrict__ dec,
    float* __restrict__ attin)
{
    const size_t idx = (size_t)blockIdx.x * 256 + threadIdx.x;
    const int col = (int)(idx & (HH - 1));
    const int row = (int)(idx >> 11);
    const int b   = row >> 11;
    const float kv = k[idx] * v[idx];
    const float r  = 1.f / (1.f + __expf(-rraw[idx]));
    const float* lwr = lw + (size_t)row * 4;
    float w = 0.f;
#pragma unroll
    for (int d = 0; d < DD; d++)
        w += lwr[d] * (state[((size_t)b * DD + d) * HH + col] * dec[d * HH + col] + kv);
    attin[idx] = r * w;
}

__global__ __launch_bounds__(256) void km_kernel(
    const float* __restrict__ h2, const float* __restrict__ cm,
    const float* __restrict__ tmk, float* __restrict__ km)
{
    const size_t idx = (size_t)blockIdx.x * 256 + threadIdx.x;
    const int col = (int)(idx & (HH - 1));
    const int row = (int)(idx >> 11);
    const int t = row & (TT - 1);
    const int b = row >> 11;
    const float prev = (t == 0) ? cm[(size_t)b * HH + col] : h2[idx - HH];
    const float tk = tmk[col];
    km[idx] = h2[idx] * tk + prev * (1.f - tk);
}

__global__ __launch_bounds__(256) void final_kernel(
    const float* __restrict__ x1, const float* __restrict__ val,
    const float* __restrict__ gate, float* __restrict__ out)
{
    const size_t idx = (size_t)blockIdx.x * 256 + threadIdx.x;
    const float g = 1.f / (1.f + __expf(-gate[idx]));
    out[idx] = x1[idx] + val[idx] * g;
}

// ---------------------------------------------------------------------------
extern "C" void kernel_launch(void* const* d_in, const int* in_sizes, int n_in,
                              void* d_out, int out_size)
{
    const float* x       = (const float*)d_in[0];
    const float* att_st  = (const float*)d_in[1];
    const float* cm_st   = (const float*)d_in[2];
    const float* ln1_s   = (const float*)d_in[3];
    const float* ln1_b   = (const float*)d_in[4];
    const float* ln2_s   = (const float*)d_in[5];
    const float* ln2_b   = (const float*)d_in[6];
    const float* td      = (const float*)d_in[7];
    const float* lvl_w   = (const float*)d_in[8];
    const float* lvl_b   = (const float*)d_in[9];
    const float* Wv      = (const float*)d_in[10];
    const float* Wk      = (const float*)d_in[11];
    const float* Wr      = (const float*)d_in[12];
    const float* Wo      = (const float*)d_in[13];
    const float* tmk     = (const float*)d_in[14];
    const float* Wkey    = (const float*)d_in[15];
    const float* Wval    = (const float*)d_in[16];
    const float* Wgate   = (const float*)d_in[17];
    float* out = (float*)d_out;

    float *h, *v, *k, *r, *x1, *kk, *lw, *dec;
    float *WvT, *WkT, *WrT, *WoT, *WkeyT, *WvalT, *WgateT;
    cudaGetSymbolAddress((void**)&h,   g_h);
    cudaGetSymbolAddress((void**)&v,   g_v);
    cudaGetSymbolAddress((void**)&k,   g_k);
    cudaGetSymbolAddress((void**)&r,   g_r);
    cudaGetSymbolAddress((void**)&x1,  g_x1);
    cudaGetSymbolAddress((void**)&kk,  g_kk);
    cudaGetSymbolAddress((void**)&lw,  g_lw);
    cudaGetSymbolAddress((void**)&dec, g_dec);
    cudaGetSymbolAddress((void**)&WvT,   g_WvT);
    cudaGetSymbolAddress((void**)&WkT,   g_WkT);
    cudaGetSymbolAddress((void**)&WrT,   g_WrT);
    cudaGetSymbolAddress((void**)&WoT,   g_WoT);
    cudaGetSymbolAddress((void**)&WkeyT, g_WkeyT);
    cudaGetSymbolAddress((void**)&WvalT, g_WvalT);
    cudaGetSymbolAddress((void**)&WgateT,g_WgateT);

    const dim3 tb(32, 8);
    // weight transposes: out[N,K] = in[K,N]^T ; grid (C/32, R/32) over in[R,C]
    transpose_kernel<<<dim3(HH/32,  HH/32),  tb>>>(Wv,    WvT,    HH,  HH);
    transpose_kernel<<<dim3(HH/32,  HH/32),  tb>>>(Wk,    WkT,    HH,  HH);
    transpose_kernel<<<dim3(HH/32,  HH/32),  tb>>>(Wr,    WrT,    HH,  HH);
    transpose_kernel<<<dim3(HH/32,  HH/32),  tb>>>(Wo,    WoT,    HH,  HH);
    transpose_kernel<<<dim3(FFN/32, HH/32),  tb>>>(Wkey,  WkeyT,  HH,  FFN);
    transpose_kernel<<<dim3(HH/32,  FFN/32), tb>>>(Wval,  WvalT,  FFN, HH);
    transpose_kernel<<<dim3(HH/32,  FFN/32), tb>>>(Wgate, WgateT, FFN, HH);

    const dim3 gHH(HH / 128, MM / 128);     // N=2048: (16, 64)
    const dim3 gFF(FFN / 128, MM / 128);    // N=8192: (64, 64)
    const int ELEM_BLKS = (MM * HH) / 256;

    // --- attention half ---
    ln_kernel<<<MM, 256>>>(x, ln1_s, ln1_b, h);
    mma_gemm_kernel<0><<<gHH, 256>>>(h, WvT, nullptr, v, MM, HH, HH);
    mma_gemm_kernel<0><<<gHH, 256>>>(h, WkT, nullptr, k, MM, HH, HH);
    mma_gemm_kernel<0><<<gHH, 256>>>(h, WrT, nullptr, r, MM, HH, HH);
    lvl_kernel<<<MM, 256>>>(h, lvl_w, lvl_b, lw);
    decay_kernel<<<(DD * HH + 255) / 256, 256>>>(td, dec);
    attn_elem_kernel<<<ELEM_BLKS, 256>>>(v, k, r, lw, att_st, dec, h);   // attin -> h
    mma_gemm_kernel<1><<<gHH, 256>>>(h, WoT, x, x1, MM, HH, HH);

    // --- channel-mix half ---
    ln_kernel<<<MM, 256>>>(x1, ln2_s, ln2_b, v);                          // h2 -> v
    km_kernel<<<ELEM_BLKS, 256>>>(v, cm_st, tmk, k);                      // km -> k
    mma_gemm_kernel<2><<<gFF, 256>>>(k, WkeyT, nullptr, kk, MM, FFN, HH);
    mma_gemm_kernel<0><<<gHH, 256>>>(kk, WvalT,  nullptr, r, MM, HH, FFN);
    mma_gemm_kernel<0><<<gHH, 256>>>(kk, WgateT, nullptr, h, MM, HH, FFN);
    final_kernel<<<ELEM_BLKS, 256>>>(x1, r, h, out);
}

// round 10
// speedup vs baseline: 6.6798x; 1.2814x over previous
#include <cuda_runtime.h>
#include <cuda_fp16.h>
#include <cstdint>

// Problem constants
#define BB 4
#define TT 2048
#define HH 2048
#define DD 4
#define FFN 8192
#define MM (BB * TT)          // 8192 tokens

// Scratch (device globals: allocation-free per harness rules)
__device__ __half g_hh [MM * HH];    // h (LN1, half) -> later h2 (LN2)
__device__ __half g_att[MM * HH];    // attin (half)  -> later km
__device__ __half g_kkh[MM * FFN];   // kk (half)
__device__ float  g_v  [MM * HH];    // v      -> later gate
__device__ float  g_k  [MM * HH];    // k
__device__ float  g_r  [MM * HH];    // r raw  -> later val
__device__ float  g_x1 [MM * HH];    // x1
__device__ float  g_lw [MM * DD];    // level softmax weights
__device__ float  g_dec[DD * HH];    // decay
// Transposed fp16 weights ([N,K] row-major for mma.sync row.col B operand)
__device__ __half g_WvT  [HH * HH];
__device__ __half g_WkT  [HH * HH];
__device__ __half g_WrT  [HH * HH];
__device__ __half g_WoT  [HH * HH];
__device__ __half g_WkeyT[FFN * HH];
__device__ __half g_WvalT[HH * FFN];
__device__ __half g_WgateT[HH * FFN];

// ---------------------------------------------------------------------------
__device__ __forceinline__ void mma_f16(float c[4], const uint32_t a[4], const uint32_t b[2]) {
    asm volatile(
        "mma.sync.aligned.m16n8k16.row.col.f32.f16.f16.f32 "
        "{%0,%1,%2,%3}, {%4,%5,%6,%7}, {%8,%9}, {%0,%1,%2,%3};"
        : "+f"(c[0]), "+f"(c[1]), "+f"(c[2]), "+f"(c[3])
        : "r"(a[0]), "r"(a[1]), "r"(a[2]), "r"(a[3]), "r"(b[0]), "r"(b[1]));
}

__device__ __forceinline__ void cp_async16(uint32_t smem_addr, const void* gptr) {
    asm volatile("cp.async.ca.shared.global [%0], [%1], 16;" :: "r"(smem_addr), "l"(gptr));
}
__device__ __forceinline__ void cp_commit() {
    asm volatile("cp.async.commit_group;" ::: "memory");
}
__device__ __forceinline__ void cp_wait0() {
    asm volatile("cp.async.wait_group 0;" ::: "memory");
}

// ===========================================================================
// Tensor-core fp16 GEMM (fp32 accum): C[M,N] = A[M,K] @ Bt[N,K]^T
// A, Bt are __half row-major. Block tile 128x128, BK=32, 128 threads
// (4 warps = 2x2), warp tile 64x64, cp.async double-buffered SMEM.
// EPI: 0 plain, 1 +Res(float), 2 relu(.)^2.  OutT: float or __half.
// Requires M%128==0, N%128==0, K%32==0.
// ===========================================================================
template <int EPI, typename OutT>
__global__ __launch_bounds__(128, 2) void mma_gemm_kernel(
    const __half* __restrict__ A, const __half* __restrict__ Bt,
    const float* __restrict__ Res, OutT* __restrict__ C,
    int M, int N, int K)
{
    __shared__ uint32_t As[2][128][20];   // [buf][m][k-pair], 16 used + 4 pad
    __shared__ uint32_t Bs[2][128][20];   // [buf][n][k-pair]

    const int tid = threadIdx.x;
    const int wid = tid >> 5, lane = tid & 31;
    const int wm = wid & 1, wn = wid >> 1;        // 2(m) x 2(n) warp grid
    const int group = lane >> 2, tg = lane & 3;   // mma fragment coords
    const int bm = blockIdx.y * 128, bn = blockIdx.x * 128;

    // loader: thread t owns row t (A and B), 4 x 16B chunks each
    const __half* Arow = A  + (size_t)(bm + tid) * K;
    const __half* Brow = Bt + (size_t)(bn + tid) * K;
    uint32_t sAr[2], sBr[2];
    {
        const uint32_t a0 = (uint32_t)__cvta_generic_to_shared(&As[0][tid][0]);
        const uint32_t a1 = (uint32_t)__cvta_generic_to_shared(&As[1][tid][0]);
        const uint32_t b0 = (uint32_t)__cvta_generic_to_shared(&Bs[0][tid][0]);
        const uint32_t b1 = (uint32_t)__cvta_generic_to_shared(&Bs[1][tid][0]);
        sAr[0] = a0; sAr[1] = a1; sBr[0] = b0; sBr[1] = b1;
    }

    auto load_async = [&](int k0, int buf) {
#pragma unroll
        for (int cg = 0; cg < 4; cg++) {
            cp_async16(sAr[buf] + cg * 16, Arow + k0 + cg * 8);
            cp_async16(sBr[buf] + cg * 16, Brow + k0 + cg * 8);
        }
        cp_commit();
    };

    float c[4][8][4];
#pragma unroll
    for (int mi = 0; mi < 4; mi++)
#pragma unroll
        for (int ni = 0; ni < 8; ni++)
#pragma unroll
            for (int j = 0; j < 4; j++) c[mi][ni][j] = 0.f;

    load_async(0, 0);
    cp_wait0();
    __syncthreads();

    const int nt = K >> 5;
    for (int t = 0; t < nt; ++t) {
        const int buf = t & 1;
        if (t + 1 < nt) load_async((t + 1) << 5, buf ^ 1);
#pragma unroll
        for (int ks = 0; ks < 2; ++ks) {
            const int k0 = ks * 8;                 // uint col base (k16 block)
            uint32_t af[4][4], bf[8][2];
#pragma unroll
            for (int mi = 0; mi < 4; mi++) {
                const int rb = wm * 64 + mi * 16;
                af[mi][0] = As[buf][rb + group][k0 + tg];
                af[mi][1] = As[buf][rb + group + 8][k0 + tg];
                af[mi][2] = As[buf][rb + group][k0 + tg + 4];
                af[mi][3] = As[buf][rb + group + 8][k0 + tg + 4];
            }
#pragma unroll
            for (int ni = 0; ni < 8; ni++) {
                const int nb = wn * 64 + ni * 8;
                bf[ni][0] = Bs[buf][nb + group][k0 + tg];
                bf[ni][1] = Bs[buf][nb + group][k0 + tg + 4];
            }
#pragma unroll
            for (int mi = 0; mi < 4; mi++)
#pragma unroll
                for (int ni = 0; ni < 8; ni++)
                    mma_f16(c[mi][ni], af[mi], bf[ni]);
        }
        if (t + 1 < nt) { cp_wait0(); }
        __syncthreads();
    }

    // epilogue: c0,c1 -> (m0, n0..n0+1); c2,c3 -> (m0+8, n0..n0+1)
#pragma unroll
    for (int mi = 0; mi < 4; mi++) {
        const int m0 = bm + wm * 64 + mi * 16 + group;
#pragma unroll
        for (int ni = 0; ni < 8; ni++) {
            const int n0 = bn + wn * 64 + ni * 8 + tg * 2;
            float2 lo = make_float2(c[mi][ni][0], c[mi][ni][1]);
            float2 hi = make_float2(c[mi][ni][2], c[mi][ni][3]);
            if (EPI == 1) {
                const float2 r0 = *(const float2*)(Res + (size_t)m0 * N + n0);
                const float2 r1 = *(const float2*)(Res + (size_t)(m0 + 8) * N + n0);
                lo.x += r0.x; lo.y += r0.y; hi.x += r1.x; hi.y += r1.y;
            }
            if (EPI == 2) {
                lo.x = fmaxf(lo.x, 0.f); lo.x *= lo.x;
                lo.y = fmaxf(lo.y, 0.f); lo.y *= lo.y;
                hi.x = fmaxf(hi.x, 0.f); hi.x *= hi.x;
                hi.y = fmaxf(hi.y, 0.f); hi.y *= hi.y;
            }
            if (sizeof(OutT) == 2) {
                *(__half2*)((__half*)C + (size_t)m0 * N + n0)       = __floats2half2_rn(lo.x, lo.y);
                *(__half2*)((__half*)C + (size_t)(m0 + 8) * N + n0) = __floats2half2_rn(hi.x, hi.y);
            } else {
                *(float2*)((float*)C + (size_t)m0 * N + n0)       = lo;
                *(float2*)((float*)C + (size_t)(m0 + 8) * N + n0) = hi;
            }
        }
    }
}

// ---------------------------------------------------------------------------
// Transpose + fp16 convert: in[R,C] fp32 -> out[C,R] fp16
// ---------------------------------------------------------------------------
__global__ __launch_bounds__(256) void transpose_h_kernel(
    const float* __restrict__ in, __half* __restrict__ out, int R, int C)
{
    __shared__ float tile[32][33];
    const int c0 = blockIdx.x * 32, r0 = blockIdx.y * 32;
    for (int i = threadIdx.y; i < 32; i += 8)
        tile[i][threadIdx.x] = in[(size_t)(r0 + i) * C + c0 + threadIdx.x];
    __syncthreads();
    for (int i = threadIdx.y; i < 32; i += 8)
        out[(size_t)(c0 + i) * R + r0 + threadIdx.x] = __float2half(tile[threadIdx.x][i]);
}

// ---------------------------------------------------------------------------
// LayerNorm -> fp16: one block per row of H=2048
// ---------------------------------------------------------------------------
__global__ __launch_bounds__(256) void ln_kernel(
    const float* __restrict__ x, const float* __restrict__ s,
    const float* __restrict__ bvec, __half* __restrict__ out)
{
    const int row = blockIdx.x;
    const float* xr = x + (size_t)row * HH;
    float sum = 0.f, sq = 0.f;
    for (int i = threadIdx.x; i < HH; i += 256) {
        float v = xr[i];
        sum += v;
        sq = fmaf(v, v, sq);
    }
    for (int o = 16; o; o >>= 1) {
        sum += __shfl_down_sync(0xffffffffu, sum, o);
        sq  += __shfl_down_sync(0xffffffffu, sq,  o);
    }
    __shared__ float s1[8], s2[8];
    const int lane = threadIdx.x & 31, w = threadIdx.x >> 5;
    if (!lane) { s1[w] = sum; s2[w] = sq; }
    __syncthreads();
    if (w == 0) {
        sum = (lane < 8) ? s1[lane] : 0.f;
        sq  = (lane < 8) ? s2[lane] : 0.f;
        for (int o = 4; o; o >>= 1) {
            sum += __shfl_down_sync(0xffffffffu, sum, o);
            sq  += __shfl_down_sync(0xffffffffu, sq,  o);
        }
        if (!lane) { s1[0] = sum; s2[0] = sq; }
    }
    __syncthreads();
    const float mean = s1[0] * (1.f / HH);
    const float var  = s2[0] * (1.f / HH) - mean * mean;
    const float inv  = rsqrtf(var + 1e-5f);
    __half* orow = out + (size_t)row * HH;
    for (int i = threadIdx.x; i < HH; i += 256)
        orow[i] = __float2half((xr[i] - mean) * inv * s[i] + bvec[i]);
}

// ---------------------------------------------------------------------------
// Level projection + softmax over D=4 (h is fp16): one block per row
// ---------------------------------------------------------------------------
__global__ __launch_bounds__(256) void lvl_kernel(
    const __half* __restrict__ h, const float* __restrict__ W,
    const float* __restrict__ bias, float* __restrict__ lw)
{
    const int row = blockIdx.x;
    const __half* hr = h + (size_t)row * HH;
    float a0 = 0.f, a1 = 0.f, a2 = 0.f, a3 = 0.f;
    for (int i = threadIdx.x; i < HH; i += 256) {
        const float hv = __half2float(hr[i]);
        const float4 w = *(const float4*)(W + (size_t)i * 4);
        a0 = fmaf(hv, w.x, a0); a1 = fmaf(hv, w.y, a1);
        a2 = fmaf(hv, w.z, a2); a3 = fmaf(hv, w.w, a3);
    }
    for (int o = 16; o; o >>= 1) {
        a0 += __shfl_down_sync(0xffffffffu, a0, o);
        a1 += __shfl_down_sync(0xffffffffu, a1, o);
        a2 += __shfl_down_sync(0xffffffffu, a2, o);
        a3 += __shfl_down_sync(0xffffffffu, a3, o);
    }
    __shared__ float red[8][4];
    const int lane = threadIdx.x & 31, w = threadIdx.x >> 5;
    if (!lane) { red[w][0] = a0; red[w][1] = a1; red[w][2] = a2; red[w][3] = a3; }
    __syncthreads();
    if (threadIdx.x == 0) {
        float s[4];
        for (int d = 0; d < 4; d++) {
            s[d] = bias[d];
            for (int ww = 0; ww < 8; ww++) s[d] += red[ww][d];
        }
        float mx = fmaxf(fmaxf(s[0], s[1]), fmaxf(s[2], s[3]));
        float e[4], tot = 0.f;
        for (int d = 0; d < 4; d++) { e[d] = expf(s[d] - mx); tot += e[d]; }
        const float rinv = 1.f / tot;
        for (int d = 0; d < 4; d++) lw[(size_t)row * 4 + d] = e[d] * rinv;
    }
}

__global__ void decay_kernel(const float* __restrict__ td, float* __restrict__ dec)
{
    const int i = blockIdx.x * blockDim.x + threadIdx.x;
    if (i < DD * HH) dec[i] = expf(-expf(td[i]));
}

// attin(half) = sigmoid(r) * sum_d lw_d * (state*decay + k*v)
__global__ __launch_bounds__(256) void attn_elem_kernel(
    const float* __restrict__ v, const float* __restrict__ k,
    const float* __restrict__ rraw, const float* __restrict__ lw,
    const float* __restrict__ state, const float* __restrict__ dec,
    __half* __restrict__ attin)
{
    const size_t idx = (size_t)blockIdx.x * 256 + threadIdx.x;
    const int col = (int)(idx & (HH - 1));
    const int row = (int)(idx >> 11);
    const int b   = row >> 11;
    const float kv = k[idx] * v[idx];
    const float r  = 1.f / (1.f + __expf(-rraw[idx]));
    const float* lwr = lw + (size_t)row * 4;
    float w = 0.f;
#pragma unroll
    for (int d = 0; d < DD; d++)
        w += lwr[d] * (state[((size_t)b * DD + d) * HH + col] * dec[d * HH + col] + kv);
    attin[idx] = __float2half(r * w);
}

// km(half) = h2*tmk + shift(h2)*(1-tmk)
__global__ __launch_bounds__(256) void km_kernel(
    const __half* __restrict__ h2, const float* __restrict__ cm,
    const float* __restrict__ tmk, __half* __restrict__ km)
{
    const size_t idx = (size_t)blockIdx.x * 256 + threadIdx.x;
    const int col = (int)(idx & (HH - 1));
    const int row = (int)(idx >> 11);
    const int t = row & (TT - 1);
    const int b = row >> 11;
    const float prev = (t == 0) ? cm[(size_t)b * HH + col] : __half2float(h2[idx - HH]);
    const float tk = tmk[col];
    km[idx] = __float2half(__half2float(h2[idx]) * tk + prev * (1.f - tk));
}

__global__ __launch_bounds__(256) void final_kernel(
    const float* __restrict__ x1, const float* __restrict__ val,
    const float* __restrict__ gate, float* __restrict__ out)
{
    const size_t idx = (size_t)blockIdx.x * 256 + threadIdx.x;
    const float g = 1.f / (1.f + __expf(-gate[idx]));
    out[idx] = x1[idx] + val[idx] * g;
}

// ---------------------------------------------------------------------------
extern "C" void kernel_launch(void* const* d_in, const int* in_sizes, int n_in,
                              void* d_out, int out_size)
{
    const float* x       = (const float*)d_in[0];
    const float* att_st  = (const float*)d_in[1];
    const float* cm_st   = (const float*)d_in[2];
    const float* ln1_s   = (const float*)d_in[3];
    const float* ln1_b   = (const float*)d_in[4];
    const float* ln2_s   = (const float*)d_in[5];
    const float* ln2_b   = (const float*)d_in[6];
    const float* td      = (const float*)d_in[7];
    const float* lvl_w   = (const float*)d_in[8];
    const float* lvl_b   = (const float*)d_in[9];
    const float* Wv      = (const float*)d_in[10];
    const float* Wk      = (const float*)d_in[11];
    const float* Wr      = (const float*)d_in[12];
    const float* Wo      = (const float*)d_in[13];
    const float* tmk     = (const float*)d_in[14];
    const float* Wkey    = (const float*)d_in[15];
    const float* Wval    = (const float*)d_in[16];
    const float* Wgate   = (const float*)d_in[17];
    float* out = (float*)d_out;

    __half *hh, *att, *kkh;
    float *v, *k, *r, *x1, *lw, *dec;
    __half *WvT, *WkT, *WrT, *WoT, *WkeyT, *WvalT, *WgateT;
    cudaGetSymbolAddress((void**)&hh,  g_hh);
    cudaGetSymbolAddress((void**)&att, g_att);
    cudaGetSymbolAddress((void**)&kkh, g_kkh);
    cudaGetSymbolAddress((void**)&v,   g_v);
    cudaGetSymbolAddress((void**)&k,   g_k);
    cudaGetSymbolAddress((void**)&r,   g_r);
    cudaGetSymbolAddress((void**)&x1,  g_x1);
    cudaGetSymbolAddress((void**)&lw,  g_lw);
    cudaGetSymbolAddress((void**)&dec, g_dec);
    cudaGetSymbolAddress((void**)&WvT,   g_WvT);
    cudaGetSymbolAddress((void**)&WkT,   g_WkT);
    cudaGetSymbolAddress((void**)&WrT,   g_WrT);
    cudaGetSymbolAddress((void**)&WoT,   g_WoT);
    cudaGetSymbolAddress((void**)&WkeyT, g_WkeyT);
    cudaGetSymbolAddress((void**)&WvalT, g_WvalT);
    cudaGetSymbolAddress((void**)&WgateT,g_WgateT);

    const dim3 tb(32, 8);
    // weight transposes (fp32 -> fp16): out[N,K] = in[K,N]^T
    transpose_h_kernel<<<dim3(HH/32,  HH/32),  tb>>>(Wv,    WvT,    HH,  HH);
    transpose_h_kernel<<<dim3(HH/32,  HH/32),  tb>>>(Wk,    WkT,    HH,  HH);
    transpose_h_kernel<<<dim3(HH/32,  HH/32),  tb>>>(Wr,    WrT,    HH,  HH);
    transpose_h_kernel<<<dim3(HH/32,  HH/32),  tb>>>(Wo,    WoT,    HH,  HH);
    transpose_h_kernel<<<dim3(FFN/32, HH/32),  tb>>>(Wkey,  WkeyT,  HH,  FFN);
    transpose_h_kernel<<<dim3(HH/32,  FFN/32), tb>>>(Wval,  WvalT,  FFN, HH);
    transpose_h_kernel<<<dim3(HH/32,  FFN/32), tb>>>(Wgate, WgateT, FFN, HH);

    const dim3 gHH(HH / 128, MM / 128);     // N=2048: (16, 64)
    const dim3 gFF(FFN / 128, MM / 128);    // N=8192: (64, 64)
    const int ELEM_BLKS = (MM * HH) / 256;

    // --- attention half ---
    ln_kernel<<<MM, 256>>>(x, ln1_s, ln1_b, hh);
    mma_gemm_kernel<0, float><<<gHH, 128>>>(hh, WvT, nullptr, v, MM, HH, HH);
    mma_gemm_kernel<0, float><<<gHH, 128>>>(hh, WkT, nullptr, k, MM, HH, HH);
    mma_gemm_kernel<0, float><<<gHH, 128>>>(hh, WrT, nullptr, r, MM, HH, HH);
    lvl_kernel<<<MM, 256>>>(hh, lvl_w, lvl_b, lw);
    decay_kernel<<<(DD * HH + 255) / 256, 256>>>(td, dec);
    attn_elem_kernel<<<ELEM_BLKS, 256>>>(v, k, r, lw, att_st, dec, att);
    mma_gemm_kernel<1, float><<<gHH, 128>>>(att, WoT, x, x1, MM, HH, HH);

    // --- channel-mix half ---
    ln_kernel<<<MM, 256>>>(x1, ln2_s, ln2_b, hh);                         // h2 -> hh
    km_kernel<<<ELEM_BLKS, 256>>>(hh, cm_st, tmk, att);                   // km -> att
    mma_gemm_kernel<2, __half><<<gFF, 128>>>(att, WkeyT, nullptr, kkh, MM, FFN, HH);
    mma_gemm_kernel<0, float><<<gHH, 128>>>(kkh, WvalT,  nullptr, r, MM, HH, FFN);  // val
    mma_gemm_kernel<0, float><<<gHH, 128>>>(kkh, WgateT, nullptr, v, MM, HH, FFN);  // gate
    final_kernel<<<ELEM_BLKS, 256>>>(x1, r, v, out);
}

// round 12
// speedup vs baseline: 7.3030x; 1.0933x over previous
#include <cuda_runtime.h>
#include <cuda_fp16.h>
#include <cstdint>

// Problem constants
#define BB 4
#define TT 2048
#define HH 2048
#define DD 4
#define FFN 8192
#define MM (BB * TT)          // 8192 tokens

// Scratch (device globals: allocation-free per harness rules)
__device__ __half g_hh [MM * HH];    // h (LN1, half) -> later h2 (LN2)
__device__ __half g_att[MM * HH];    // attin (half)  -> later km
__device__ __half g_kkh[MM * FFN];   // kk (half)
__device__ __half g_vh [MM * HH];    // v (half)
__device__ __half g_kh [MM * HH];    // k (half)
__device__ __half g_rh [MM * HH];    // r raw (half)
__device__ float  g_val[MM * HH];    // val (float)
__device__ float  g_gat[MM * HH];    // gate (float)
__device__ float  g_x1 [MM * HH];    // x1
__device__ float  g_lw [MM * DD];    // level softmax weights
__device__ float  g_dec[DD * HH];    // decay
// Transposed fp16 weights ([N,K] row-major for mma.sync row.col B operand)
__device__ __half g_WvT  [HH * HH];
__device__ __half g_WkT  [HH * HH];
__device__ __half g_WrT  [HH * HH];
__device__ __half g_WoT  [HH * HH];
__device__ __half g_WkeyT[FFN * HH];
__device__ __half g_WvalT[HH * FFN];
__device__ __half g_WgateT[HH * FFN];

// ---------------------------------------------------------------------------
__device__ __forceinline__ void mma_f16(float c[4], const uint32_t a[4], const uint32_t b[2]) {
    asm volatile(
        "mma.sync.aligned.m16n8k16.row.col.f32.f16.f16.f32 "
        "{%0,%1,%2,%3}, {%4,%5,%6,%7}, {%8,%9}, {%0,%1,%2,%3};"
        : "+f"(c[0]), "+f"(c[1]), "+f"(c[2]), "+f"(c[3])
        : "r"(a[0]), "r"(a[1]), "r"(a[2]), "r"(a[3]), "r"(b[0]), "r"(b[1]));
}

__device__ __forceinline__ void ldsm_x4(uint32_t& r0, uint32_t& r1, uint32_t& r2, uint32_t& r3,
                                        uint32_t addr) {
    asm volatile("ldmatrix.sync.aligned.m8n8.x4.shared.b16 {%0,%1,%2,%3}, [%4];"
                 : "=r"(r0), "=r"(r1), "=r"(r2), "=r"(r3) : "r"(addr));
}

__device__ __forceinline__ void cp_async16(uint32_t smem_addr, const void* gptr) {
    asm volatile("cp.async.ca.shared.global [%0], [%1], 16;" :: "r"(smem_addr), "l"(gptr));
}
__device__ __forceinline__ void cp_commit() {
    asm volatile("cp.async.commit_group;" ::: "memory");
}
__device__ __forceinline__ void cp_wait0() {
    asm volatile("cp.async.wait_group 0;" ::: "memory");
}

// ===========================================================================
// Tensor-core fp16 GEMM (fp32 accum): C[M,N] = A[M,K] @ Bt[N,K]^T
// A, Bt are __half row-major. Block tile 128x128, BK=32, 128 threads
// (4 warps = 2x2), warp tile 64x64, cp.async double-buffered SMEM,
// ldmatrix fragment loads. EPI: 0 plain, 1 +Res(float), 2 relu(.)^2.
// OutT: float or __half.  Requires M%128==0, N%128==0, K%32==0.
// ===========================================================================
template <int EPI, typename OutT>
__global__ __launch_bounds__(128, 2) void mma_gemm_kernel(
    const __half* __restrict__ A, const __half* __restrict__ Bt,
    const float* __restrict__ Res, OutT* __restrict__ C,
    int M, int N, int K)
{
    __shared__ uint32_t As[2][128][20];   // [buf][m][k-pair], 16 used + 4 pad (80B row)
    __shared__ uint32_t Bs[2][128][20];   // [buf][n][k-pair]

    const int tid = threadIdx.x;
    const int wid = tid >> 5, lane = tid & 31;
    const int wm = wid & 1, wn = wid >> 1;        // 2(m) x 2(n) warp grid
    const int group = lane >> 2, tg = lane & 3;   // mma fragment coords
    const int bm = blockIdx.y * 128, bn = blockIdx.x * 128;

    // loader: thread t owns row t (A and B), 4 x 16B chunks each
    const __half* Arow = A  + (size_t)(bm + tid) * K;
    const __half* Brow = Bt + (size_t)(bn + tid) * K;
    uint32_t sAr[2], sBr[2];
    sAr[0] = (uint32_t)__cvta_generic_to_shared(&As[0][tid][0]);
    sAr[1] = (uint32_t)__cvta_generic_to_shared(&As[1][tid][0]);
    sBr[0] = (uint32_t)__cvta_generic_to_shared(&Bs[0][tid][0]);
    sBr[1] = (uint32_t)__cvta_generic_to_shared(&Bs[1][tid][0]);

    // ldmatrix per-lane source addresses
    // A (x4 covers m16 x k16): matrices {rows 0-7 kLo, rows 8-15 kLo, rows 0-7 kHi, rows 8-15 kHi}
    const int arow_l = wm * 64 + (lane & 7) + ((lane >> 3) & 1) * 8;
    const int acol_l = (lane >> 4) << 2;                    // 0 or 4 (uint col)
    // B (x4 covers n16 x k16 = ni pair): matrices {n0-7 kLo, n0-7 kHi, n8-15 kLo, n8-15 kHi}
    const int brow_l = wn * 64 + ((lane >> 4) << 3) + (lane & 7);
    const int bcol_l = ((lane >> 3) & 1) << 2;              // 0 or 4
    uint32_t aLd[2], bLd[2];
    aLd[0] = (uint32_t)__cvta_generic_to_shared(&As[0][arow_l][acol_l]);
    aLd[1] = (uint32_t)__cvta_generic_to_shared(&As[1][arow_l][acol_l]);
    bLd[0] = (uint32_t)__cvta_generic_to_shared(&Bs[0][brow_l][bcol_l]);
    bLd[1] = (uint32_t)__cvta_generic_to_shared(&Bs[1][brow_l][bcol_l]);

    auto load_async = [&](int k0, int buf) {
#pragma unroll
        for (int cg = 0; cg < 4; cg++) {
            cp_async16(sAr[buf] + cg * 16, Arow + k0 + cg * 8);
            cp_async16(sBr[buf] + cg * 16, Brow + k0 + cg * 8);
        }
        cp_commit();
    };

    float c[4][8][4];
#pragma unroll
    for (int mi = 0; mi < 4; mi++)
#pragma unroll
        for (int ni = 0; ni < 8; ni++)
#pragma unroll
            for (int j = 0; j < 4; j++) c[mi][ni][j] = 0.f;

    load_async(0, 0);
    cp_wait0();
    __syncthreads();

    const int nt = K >> 5;
    for (int t = 0; t < nt; ++t) {
        const int buf = t & 1;
        if (t + 1 < nt) load_async((t + 1) << 5, buf ^ 1);
#pragma unroll
        for (int ks = 0; ks < 2; ++ks) {
            const int kb = ks * 32;                // byte offset of k16 block (8 uints)
            uint32_t af[4][4], bf[8][2];
#pragma unroll
            for (int mi = 0; mi < 4; mi++)
                ldsm_x4(af[mi][0], af[mi][1], af[mi][2], af[mi][3],
                        aLd[buf] + mi * 16 * 80 + kb);
#pragma unroll
            for (int p = 0; p < 4; p++)
                ldsm_x4(bf[2 * p][0], bf[2 * p][1], bf[2 * p + 1][0], bf[2 * p + 1][1],
                        bLd[buf] + p * 16 * 80 + kb);
#pragma unroll
            for (int mi = 0; mi < 4; mi++)
#pragma unroll
                for (int ni = 0; ni < 8; ni++)
                    mma_f16(c[mi][ni], af[mi], bf[ni]);
        }
        if (t + 1 < nt) { cp_wait0(); }
        __syncthreads();
    }

    // epilogue
#pragma unroll
    for (int mi = 0; mi < 4; mi++) {
        const int m0 = bm + wm * 64 + mi * 16 + group;
#pragma unroll
        for (int ni = 0; ni < 8; ni++) {
            const int n0 = bn + wn * 64 + ni * 8 + tg * 2;
            float2 lo = make_float2(c[mi][ni][0], c[mi][ni][1]);
            float2 hi = make_float2(c[mi][ni][2], c[mi][ni][3]);
            if (EPI == 1) {
                const float2 r0 = *(const float2*)(Res + (size_t)m0 * N + n0);
                const float2 r1 = *(const float2*)(Res + (size_t)(m0 + 8) * N + n0);
                lo.x += r0.x; lo.y += r0.y; hi.x += r1.x; hi.y += r1.y;
            }
            if (EPI == 2) {
                lo.x = fmaxf(lo.x, 0.f); lo.x *= lo.x;
                lo.y = fmaxf(lo.y, 0.f); lo.y *= lo.y;
                hi.x = fmaxf(hi.x, 0.f); hi.x *= hi.x;
                hi.y = fmaxf(hi.y, 0.f); hi.y *= hi.y;
            }
            if (sizeof(OutT) == 2) {
                *(__half2*)((__half*)C + (size_t)m0 * N + n0)       = __floats2half2_rn(lo.x, lo.y);
                *(__half2*)((__half*)C + (size_t)(m0 + 8) * N + n0) = __floats2half2_rn(hi.x, hi.y);
            } else {
                *(float2*)((float*)C + (size_t)m0 * N + n0)       = lo;
                *(float2*)((float*)C + (size_t)(m0 + 8) * N + n0) = hi;
            }
        }
    }
}

// ---------------------------------------------------------------------------
// Transpose + fp16 convert: in[R,C] fp32 -> out[C,R] fp16
// ---------------------------------------------------------------------------
__global__ __launch_bounds__(256) void transpose_h_kernel(
    const float* __restrict__ in, __half* __restrict__ out, int R, int C)
{
    __shared__ float tile[32][33];
    const int c0 = blockIdx.x * 32, r0 = blockIdx.y * 32;
    for (int i = threadIdx.y; i < 32; i += 8)
        tile[i][threadIdx.x] = in[(size_t)(r0 + i) * C + c0 + threadIdx.x];
    __syncthreads();
    for (int i = threadIdx.y; i < 32; i += 8)
        out[(size_t)(c0 + i) * R + r0 + threadIdx.x] = __float2half(tile[threadIdx.x][i]);
}

// ---------------------------------------------------------------------------
// LayerNorm -> fp16: one block per row of H=2048
// ---------------------------------------------------------------------------
__global__ __launch_bounds__(256) void ln_kernel(
    const float* __restrict__ x, const float* __restrict__ s,
    const float* __restrict__ bvec, __half* __restrict__ out)
{
    const int row = blockIdx.x;
    const float* xr = x + (size_t)row * HH;
    float sum = 0.f, sq = 0.f;
    for (int i = threadIdx.x; i < HH; i += 256) {
        float v = xr[i];
        sum += v;
        sq = fmaf(v, v, sq);
    }
    for (int o = 16; o; o >>= 1) {
        sum += __shfl_down_sync(0xffffffffu, sum, o);
        sq  += __shfl_down_sync(0xffffffffu, sq,  o);
    }
    __shared__ float s1[8], s2[8];
    const int lane = threadIdx.x & 31, w = threadIdx.x >> 5;
    if (!lane) { s1[w] = sum; s2[w] = sq; }
    __syncthreads();
    if (w == 0) {
        sum = (lane < 8) ? s1[lane] : 0.f;
        sq  = (lane < 8) ? s2[lane] : 0.f;
        for (int o = 4; o; o >>= 1) {
            sum += __shfl_down_sync(0xffffffffu, sum, o);
            sq  += __shfl_down_sync(0xffffffffu, sq,  o);
        }
        if (!lane) { s1[0] = sum; s2[0] = sq; }
    }
    __syncthreads();
    const float mean = s1[0] * (1.f / HH);
    const float var  = s2[0] * (1.f / HH) - mean * mean;
    const float inv  = rsqrtf(var + 1e-5f);
    __half* orow = out + (size_t)row * HH;
    for (int i = threadIdx.x; i < HH; i += 256)
        orow[i] = __float2half((xr[i] - mean) * inv * s[i] + bvec[i]);
}

// ---------------------------------------------------------------------------
// Level projection + softmax over D=4 (h is fp16): one block per row
// ---------------------------------------------------------------------------
__global__ __launch_bounds__(256) void lvl_kernel(
    const __half* __restrict__ h, const float* __restrict__ W,
    const float* __restrict__ bias, float* __restrict__ lw)
{
    const int row = blockIdx.x;
    const __half* hr = h + (size_t)row * HH;
    float a0 = 0.f, a1 = 0.f, a2 = 0.f, a3 = 0.f;
    for (int i = threadIdx.x; i < HH; i += 256) {
        const float hv = __half2float(hr[i]);
        const float4 w = *(const float4*)(W + (size_t)i * 4);
        a0 = fmaf(hv, w.x, a0); a1 = fmaf(hv, w.y, a1);
        a2 = fmaf(hv, w.z, a2); a3 = fmaf(hv, w.w, a3);
    }
    for (int o = 16; o; o >>= 1) {
        a0 += __shfl_down_sync(0xffffffffu, a0, o);
        a1 += __shfl_down_sync(0xffffffffu, a1, o);
        a2 += __shfl_down_sync(0xffffffffu, a2, o);
        a3 += __shfl_down_sync(0xffffffffu, a3, o);
    }
    __shared__ float red[8][4];
    const int lane = threadIdx.x & 31, w = threadIdx.x >> 5;
    if (!lane) { red[w][0] = a0; red[w][1] = a1; red[w][2] = a2; red[w][3] = a3; }
    __syncthreads();
    if (threadIdx.x == 0) {
        float s[4];
        for (int d = 0; d < 4; d++) {
            s[d] = bias[d];
            for (int ww = 0; ww < 8; ww++) s[d] += red[ww][d];
        }
        float mx = fmaxf(fmaxf(s[0], s[1]), fmaxf(s[2], s[3]));
        float e[4], tot = 0.f;
        for (int d = 0; d < 4; d++) { e[d] = expf(s[d] - mx); tot += e[d]; }
        const float rinv = 1.f / tot;
        for (int d = 0; d < 4; d++) lw[(size_t)row * 4 + d] = e[d] * rinv;
    }
}

__global__ void decay_kernel(const float* __restrict__ td, float* __restrict__ dec)
{
    const int i = blockIdx.x * blockDim.x + threadIdx.x;
    if (i < DD * HH) dec[i] = expf(-expf(td[i]));
}

// attin(half) = sigmoid(r) * sum_d lw_d * (state*decay + k*v)   (v,k,r half)
__global__ __launch_bounds__(256) void attn_elem_kernel(
    const __half* __restrict__ v, const __half* __restrict__ k,
    const __half* __restrict__ rraw, const float* __restrict__ lw,
    const float* __restrict__ state, const float* __restrict__ dec,
    __half* __restrict__ attin)
{
    const size_t idx = (size_t)blockIdx.x * 256 + threadIdx.x;
    const int col = (int)(idx & (HH - 1));
    const int row = (int)(idx >> 11);
    const int b   = row >> 11;
    const float kv = __half2float(k[idx]) * __half2float(v[idx]);
    const float r  = 1.f / (1.f + __expf(-__half2float(rraw[idx])));
    const float* lwr = lw + (size_t)row * 4;
    float w = 0.f;
#pragma unroll
    for (int d = 0; d < DD; d++)
        w += lwr[d] * (state[((size_t)b * DD + d) * HH + col] * dec[d * HH + col] + kv);
    attin[idx] = __float2half(r * w);
}

// km(half) = h2*tmk + shift(h2)*(1-tmk)
__global__ __launch_bounds__(256) void km_kernel(
    const __half* __restrict__ h2, const float* __restrict__ cm,
    const float* __restrict__ tmk, __half* __restrict__ km)
{
    const size_t idx = (size_t)blockIdx.x * 256 + threadIdx.x;
    const int col = (int)(idx & (HH - 1));
    const int row = (int)(idx >> 11);
    const int t = row & (TT - 1);
    const int b = row >> 11;
    const float prev = (t == 0) ? cm[(size_t)b * HH + col] : __half2float(h2[idx - HH]);
    const float tk = tmk[col];
    km[idx] = __float2half(__half2float(h2[idx]) * tk + prev * (1.f - tk));
}

__global__ __launch_bounds__(256) void final_kernel(
    const float* __restrict__ x1, const float* __restrict__ val,
    const float* __restrict__ gate, float* __restrict__ out)
{
    const size_t idx = (size_t)blockIdx.x * 256 + threadIdx.x;
    const float g = 1.f / (1.f + __expf(-gate[idx]));
    out[idx] = x1[idx] + val[idx] * g;
}

// ---------------------------------------------------------------------------
extern "C" void kernel_launch(void* const* d_in, const int* in_sizes, int n_in,
                              void* d_out, int out_size)
{
    const float* x       = (const float*)d_in[0];
    const float* att_st  = (const float*)d_in[1];
    const float* cm_st   = (const float*)d_in[2];
    const float* ln1_s   = (const float*)d_in[3];
    const float* ln1_b   = (const float*)d_in[4];
    const float* ln2_s   = (const float*)d_in[5];
    const float* ln2_b   = (const float*)d_in[6];
    const float* td      = (const float*)d_in[7];
    const float* lvl_w   = (const float*)d_in[8];
    const float* lvl_b   = (const float*)d_in[9];
    const float* Wv      = (const float*)d_in[10];
    const float* Wk      = (const float*)d_in[11];
    const float* Wr      = (const float*)d_in[12];
    const float* Wo      = (const float*)d_in[13];
    const float* tmk     = (const float*)d_in[14];
    const float* Wkey    = (const float*)d_in[15];
    const float* Wval    = (const float*)d_in[16];
    const float* Wgate   = (const float*)d_in[17];
    float* out = (float*)d_out;

    __half *hh, *att, *kkh, *vh, *kh, *rh;
    float *val, *gat, *x1, *lw, *dec;
    __half *WvT, *WkT, *WrT, *WoT, *WkeyT, *WvalT, *WgateT;
    cudaGetSymbolAddress((void**)&hh,  g_hh);
    cudaGetSymbolAddress((void**)&att, g_att);
    cudaGetSymbolAddress((void**)&kkh, g_kkh);
    cudaGetSymbolAddress((void**)&vh,  g_vh);
    cudaGetSymbolAddress((void**)&kh,  g_kh);
    cudaGetSymbolAddress((void**)&rh,  g_rh);
    cudaGetSymbolAddress((void**)&val, g_val);
    cudaGetSymbolAddress((void**)&gat, g_gat);
    cudaGetSymbolAddress((void**)&x1,  g_x1);
    cudaGetSymbolAddress((void**)&lw,  g_lw);
    cudaGetSymbolAddress((void**)&dec, g_dec);
    cudaGetSymbolAddress((void**)&WvT,   g_WvT);
    cudaGetSymbolAddress((void**)&WkT,   g_WkT);
    cudaGetSymbolAddress((void**)&WrT,   g_WrT);
    cudaGetSymbolAddress((void**)&WoT,   g_WoT);
    cudaGetSymbolAddress((void**)&WkeyT, g_WkeyT);
    cudaGetSymbolAddress((void**)&WvalT, g_WvalT);
    cudaGetSymbolAddress((void**)&WgateT,g_WgateT);

    const dim3 tb(32, 8);
    // weight transposes (fp32 -> fp16): out[N,K] = in[K,N]^T
    transpose_h_kernel<<<dim3(HH/32,  HH/32),  tb>>>(Wv,    WvT,    HH,  HH);
    transpose_h_kernel<<<dim3(HH/32,  HH/32),  tb>>>(Wk,    WkT,    HH,  HH);
    transpose_h_kernel<<<dim3(HH/32,  HH/32),  tb>>>(Wr,    WrT,    HH,  HH);
    transpose_h_kernel<<<dim3(HH/32,  HH/32),  tb>>>(Wo,    WoT,    HH,  HH);
    transpose_h_kernel<<<dim3(FFN/32, HH/32),  tb>>>(Wkey,  WkeyT,  HH,  FFN);
    transpose_h_kernel<<<dim3(HH/32,  FFN/32), tb>>>(Wval,  WvalT,  FFN, HH);
    transpose_h_kernel<<<dim3(HH/32,  FFN/32), tb>>>(Wgate, WgateT, FFN, HH);

    const dim3 gHH(HH / 128, MM / 128);     // N=2048: (16, 64)
    const dim3 gFF(FFN / 128, MM / 128);    // N=8192: (64, 64)
    const int ELEM_BLKS = (MM * HH) / 256;

    // --- attention half ---
    ln_kernel<<<MM, 256>>>(x, ln1_s, ln1_b, hh);
    mma_gemm_kernel<0, __half><<<gHH, 128>>>(hh, WvT, nullptr, vh, MM, HH, HH);
    mma_gemm_kernel<0, __half><<<gHH, 128>>>(hh, WkT, nullptr, kh, MM, HH, HH);
    mma_gemm_kernel<0, __half><<<gHH, 128>>>(hh, WrT, nullptr, rh, MM, HH, HH);
    lvl_kernel<<<MM, 256>>>(hh, lvl_w, lvl_b, lw);
    decay_kernel<<<(DD * HH + 255) / 256, 256>>>(td, dec);
    attn_elem_kernel<<<ELEM_BLKS, 256>>>(vh, kh, rh, lw, att_st, dec, att);
    mma_gemm_kernel<1, float><<<gHH, 128>>>(att, WoT, x, x1, MM, HH, HH);

    // --- channel-mix half ---
    ln_kernel<<<MM, 256>>>(x1, ln2_s, ln2_b, hh);                         // h2 -> hh
    km_kernel<<<ELEM_BLKS, 256>>>(hh, cm_st, tmk, att);                   // km -> att
    mma_gemm_kernel<2, __half><<<gFF, 128>>>(att, WkeyT, nullptr, kkh, MM, FFN, HH);
    mma_gemm_kernel<0, float><<<gHH, 128>>>(kkh, WvalT,  nullptr, val, MM, HH, FFN);
    mma_gemm_kernel<0, float><<<gHH, 128>>>(kkh, WgateT, nullptr, gat, MM, HH, FFN);
    final_kernel<<<ELEM_BLKS, 256>>>(x1, val, gat, out);
}

// round 13
// speedup vs baseline: 7.5916x; 1.0395x over previous
#include <cuda_runtime.h>
#include <cuda_fp16.h>
#include <cstdint>

// Problem constants
#define BB 4
#define TT 2048
#define HH 2048
#define DD 4
#define FFN 8192
#define MM (BB * TT)          // 8192 tokens

// Scratch (device globals: allocation-free per harness rules)
__device__ __half g_hh [MM * HH];    // h (LN1, half) -> later h2 (LN2)
__device__ __half g_att[MM * HH];    // attin (half)  -> later km
__device__ __half g_kkh[MM * FFN];   // kk (half)
__device__ __half g_vh [MM * HH];    // v (half)
__device__ __half g_kh [MM * HH];    // k (half)
__device__ __half g_rh [MM * HH];    // r raw (half)
__device__ float  g_val[MM * HH];    // val (float)
__device__ float  g_gat[MM * HH];    // gate (float)
__device__ float  g_x1 [MM * HH];    // x1
__device__ float  g_lw [MM * DD];    // level softmax weights
__device__ float  g_dec[DD * HH];    // decay
// Transposed fp16 weights ([N,K] row-major for mma.sync row.col B operand)
__device__ __half g_WvT  [HH * HH];
__device__ __half g_WkT  [HH * HH];
__device__ __half g_WrT  [HH * HH];
__device__ __half g_WoT  [HH * HH];
__device__ __half g_WkeyT[FFN * HH];
__device__ __half g_WvalT[HH * FFN];
__device__ __half g_WgateT[HH * FFN];

// ---------------------------------------------------------------------------
__device__ __forceinline__ void mma_f16(float c[4], const uint32_t a[4], const uint32_t b[2]) {
    asm volatile(
        "mma.sync.aligned.m16n8k16.row.col.f32.f16.f16.f32 "
        "{%0,%1,%2,%3}, {%4,%5,%6,%7}, {%8,%9}, {%0,%1,%2,%3};"
        : "+f"(c[0]), "+f"(c[1]), "+f"(c[2]), "+f"(c[3])
        : "r"(a[0]), "r"(a[1]), "r"(a[2]), "r"(a[3]), "r"(b[0]), "r"(b[1]));
}

__device__ __forceinline__ void ldsm_x4(uint32_t& r0, uint32_t& r1, uint32_t& r2, uint32_t& r3,
                                        uint32_t addr) {
    asm volatile("ldmatrix.sync.aligned.m8n8.x4.shared.b16 {%0,%1,%2,%3}, [%4];"
                 : "=r"(r0), "=r"(r1), "=r"(r2), "=r"(r3) : "r"(addr));
}

__device__ __forceinline__ void cp_async16(uint32_t smem_addr, const void* gptr) {
    asm volatile("cp.async.ca.shared.global [%0], [%1], 16;" :: "r"(smem_addr), "l"(gptr));
}
__device__ __forceinline__ void cp_commit() {
    asm volatile("cp.async.commit_group;" ::: "memory");
}
__device__ __forceinline__ void cp_wait1() {
    asm volatile("cp.async.wait_group 1;" ::: "memory");
}

// ===========================================================================
// Tensor-core fp16 GEMM (fp32 accum): C[M,N] = A[M,K] @ Bt[N,K]^T
// A, Bt __half row-major. Block tile 128x128, BK=32, 128 threads (4 warps
// = 2x2), warp tile 64x64. 3-stage cp.async pipeline (wait_group 1) +
// double-buffered ldmatrix fragments. Dynamic smem 3x20KB.
// EPI: 0 plain, 1 +Res(float), 2 relu(.)^2.  OutT: float or __half.
// Requires M%128==0, N%128==0, K%32==0, K/32 >= 2.
// ===========================================================================
#define STAGE_U32 5120            // (128 A-rows + 128 B-rows) * 20 uints
#define STAGE_BYTES 20480
#define GEMM_SMEM (3 * STAGE_BYTES)

template <int EPI, typename OutT>
__global__ __launch_bounds__(128, 2) void mma_gemm_kernel(
    const __half* __restrict__ A, const __half* __restrict__ Bt,
    const float* __restrict__ Res, OutT* __restrict__ C,
    int M, int N, int K)
{
    extern __shared__ uint32_t smem[];   // [3][256][20]; rows 0-127 A, 128-255 B
    const uint32_t smem_base = (uint32_t)__cvta_generic_to_shared(smem);

    const int tid = threadIdx.x;
    const int wid = tid >> 5, lane = tid & 31;
    const int wm = wid & 1, wn = wid >> 1;        // 2(m) x 2(n) warp grid
    const int group = lane >> 2, tg = lane & 3;   // mma fragment coords
    const int bm = blockIdx.y * 128, bn = blockIdx.x * 128;

    // loader: thread t owns A-row t and B-row t, 4 x 16B chunks each
    const __half* Arow = A  + (size_t)(bm + tid) * K;
    const __half* Brow = Bt + (size_t)(bn + tid) * K;
    const uint32_t sA = smem_base + tid * 80;
    const uint32_t sB = smem_base + (128 + tid) * 80;

    // ldmatrix per-lane source byte offsets (within a stage)
    const int arow_l = wm * 64 + (lane & 7) + ((lane >> 3) & 1) * 8;
    const int acol_l = (lane >> 4) << 2;                    // 0 or 4 (uint col)
    const int brow_l = wn * 64 + ((lane >> 4) << 3) + (lane & 7);
    const int bcol_l = ((lane >> 3) & 1) << 2;
    const uint32_t aoff = (uint32_t)(arow_l * 80 + acol_l * 4);
    const uint32_t boff = (uint32_t)((128 + brow_l) * 80 + bcol_l * 4);

    auto load_async = [&](int k0, int st) {
        const uint32_t off = (uint32_t)st * STAGE_BYTES;
#pragma unroll
        for (int cg = 0; cg < 4; cg++) {
            cp_async16(sA + off + cg * 16, Arow + k0 + cg * 8);
            cp_async16(sB + off + cg * 16, Brow + k0 + cg * 8);
        }
        cp_commit();
    };

    auto ldfrag = [&](int st, int kb, uint32_t af[4][4], uint32_t bf[8][2]) {
        const uint32_t sb = smem_base + (uint32_t)st * STAGE_BYTES + (uint32_t)kb;
#pragma unroll
        for (int mi = 0; mi < 4; mi++)
            ldsm_x4(af[mi][0], af[mi][1], af[mi][2], af[mi][3], sb + aoff + mi * 1280);
#pragma unroll
        for (int p = 0; p < 4; p++)
            ldsm_x4(bf[2 * p][0], bf[2 * p][1], bf[2 * p + 1][0], bf[2 * p + 1][1],
                    sb + boff + p * 1280);
    };

    float c[4][8][4];
#pragma unroll
    for (int mi = 0; mi < 4; mi++)
#pragma unroll
        for (int ni = 0; ni < 8; ni++)
#pragma unroll
            for (int j = 0; j < 4; j++) c[mi][ni][j] = 0.f;

    auto compute = [&](uint32_t af[4][4], uint32_t bf[8][2]) {
#pragma unroll
        for (int mi = 0; mi < 4; mi++)
#pragma unroll
            for (int ni = 0; ni < 8; ni++)
                mma_f16(c[mi][ni], af[mi], bf[ni]);
    };

    const int nt = K >> 5;
    load_async(0, 0);
    load_async(32, 1);
    cp_wait1();              // stage 0 complete
    __syncthreads();

    uint32_t af0[4][4], bf0[8][2], af1[4][4], bf1[8][2];
    ldfrag(0, 0, af0, bf0);

    for (int t = 0; t < nt; ++t) {
        const int buf = t % 3;
        if (t + 2 < nt) load_async((t + 2) << 5, (t + 2) % 3);
        else cp_commit();                          // empty group keeps wait semantics
        ldfrag(buf, 32, af1, bf1);                 // ks1 fragments (prefetch)
        compute(af0, bf0);                         // ks0
        compute(af1, bf1);                         // ks1
        cp_wait1();                                // stage t+1 complete
        __syncthreads();
        if (t + 1 < nt) ldfrag((t + 1) % 3, 0, af0, bf0);
    }

    // epilogue
#pragma unroll
    for (int mi = 0; mi < 4; mi++) {
        const int m0 = bm + wm * 64 + mi * 16 + group;
#pragma unroll
        for (int ni = 0; ni < 8; ni++) {
            const int n0 = bn + wn * 64 + ni * 8 + tg * 2;
            float2 lo = make_float2(c[mi][ni][0], c[mi][ni][1]);
            float2 hi = make_float2(c[mi][ni][2], c[mi][ni][3]);
            if (EPI == 1) {
                const float2 r0 = *(const float2*)(Res + (size_t)m0 * N + n0);
                const float2 r1 = *(const float2*)(Res + (size_t)(m0 + 8) * N + n0);
                lo.x += r0.x; lo.y += r0.y; hi.x += r1.x; hi.y += r1.y;
            }
            if (EPI == 2) {
                lo.x = fmaxf(lo.x, 0.f); lo.x *= lo.x;
                lo.y = fmaxf(lo.y, 0.f); lo.y *= lo.y;
                hi.x = fmaxf(hi.x, 0.f); hi.x *= hi.x;
                hi.y = fmaxf(hi.y, 0.f); hi.y *= hi.y;
            }
            if (sizeof(OutT) == 2) {
                *(__half2*)((__half*)C + (size_t)m0 * N + n0)       = __floats2half2_rn(lo.x, lo.y);
                *(__half2*)((__half*)C + (size_t)(m0 + 8) * N + n0) = __floats2half2_rn(hi.x, hi.y);
            } else {
                *(float2*)((float*)C + (size_t)m0 * N + n0)       = lo;
                *(float2*)((float*)C + (size_t)(m0 + 8) * N + n0) = hi;
            }
        }
    }
}

// ---------------------------------------------------------------------------
// Transpose + fp16 convert: in[R,C] fp32 -> out[C,R] fp16
// ---------------------------------------------------------------------------
__global__ __launch_bounds__(256) void transpose_h_kernel(
    const float* __restrict__ in, __half* __restrict__ out, int R, int C)
{
    __shared__ float tile[32][33];
    const int c0 = blockIdx.x * 32, r0 = blockIdx.y * 32;
    for (int i = threadIdx.y; i < 32; i += 8)
        tile[i][threadIdx.x] = in[(size_t)(r0 + i) * C + c0 + threadIdx.x];
    __syncthreads();
    for (int i = threadIdx.y; i < 32; i += 8)
        out[(size_t)(c0 + i) * R + r0 + threadIdx.x] = __float2half(tile[threadIdx.x][i]);
}

// ---------------------------------------------------------------------------
// LayerNorm -> fp16: one block per row of H=2048
// ---------------------------------------------------------------------------
__global__ __launch_bounds__(256) void ln_kernel(
    const float* __restrict__ x, const float* __restrict__ s,
    const float* __restrict__ bvec, __half* __restrict__ out)
{
    const int row = blockIdx.x;
    const float* xr = x + (size_t)row * HH;
    float sum = 0.f, sq = 0.f;
    for (int i = threadIdx.x; i < HH; i += 256) {
        float v = xr[i];
        sum += v;
        sq = fmaf(v, v, sq);
    }
    for (int o = 16; o; o >>= 1) {
        sum += __shfl_down_sync(0xffffffffu, sum, o);
        sq  += __shfl_down_sync(0xffffffffu, sq,  o);
    }
    __shared__ float s1[8], s2[8];
    const int lane = threadIdx.x & 31, w = threadIdx.x >> 5;
    if (!lane) { s1[w] = sum; s2[w] = sq; }
    __syncthreads();
    if (w == 0) {
        sum = (lane < 8) ? s1[lane] : 0.f;
        sq  = (lane < 8) ? s2[lane] : 0.f;
        for (int o = 4; o; o >>= 1) {
            sum += __shfl_down_sync(0xffffffffu, sum, o);
            sq  += __shfl_down_sync(0xffffffffu, sq,  o);
        }
        if (!lane) { s1[0] = sum; s2[0] = sq; }
    }
    __syncthreads();
    const float mean = s1[0] * (1.f / HH);
    const float var  = s2[0] * (1.f / HH) - mean * mean;
    const float inv  = rsqrtf(var + 1e-5f);
    __half* orow = out + (size_t)row * HH;
    for (int i = threadIdx.x; i < HH; i += 256)
        orow[i] = __float2half((xr[i] - mean) * inv * s[i] + bvec[i]);
}

// ---------------------------------------------------------------------------
// Level projection + softmax over D=4 (h is fp16): one block per row
// ---------------------------------------------------------------------------
__global__ __launch_bounds__(256) void lvl_kernel(
    const __half* __restrict__ h, const float* __restrict__ W,
    const float* __restrict__ bias, float* __restrict__ lw)
{
    const int row = blockIdx.x;
    const __half* hr = h + (size_t)row * HH;
    float a0 = 0.f, a1 = 0.f, a2 = 0.f, a3 = 0.f;
    for (int i = threadIdx.x; i < HH; i += 256) {
        const float hv = __half2float(hr[i]);
        const float4 w = *(const float4*)(W + (size_t)i * 4);
        a0 = fmaf(hv, w.x, a0); a1 = fmaf(hv, w.y, a1);
        a2 = fmaf(hv, w.z, a2); a3 = fmaf(hv, w.w, a3);
    }
    for (int o = 16; o; o >>= 1) {
        a0 += __shfl_down_sync(0xffffffffu, a0, o);
        a1 += __shfl_down_sync(0xffffffffu, a1, o);
        a2 += __shfl_down_sync(0xffffffffu, a2, o);
        a3 += __shfl_down_sync(0xffffffffu, a3, o);
    }
    __shared__ float red[8][4];
    const int lane = threadIdx.x & 31, w = threadIdx.x >> 5;
    if (!lane) { red[w][0] = a0; red[w][1] = a1; red[w][2] = a2; red[w][3] = a3; }
    __syncthreads();
    if (threadIdx.x == 0) {
        float s[4];
        for (int d = 0; d < 4; d++) {
            s[d] = bias[d];
            for (int ww = 0; ww < 8; ww++) s[d] += red[ww][d];
        }
        float mx = fmaxf(fmaxf(s[0], s[1]), fmaxf(s[2], s[3]));
        float e[4], tot = 0.f;
        for (int d = 0; d < 4; d++) { e[d] = expf(s[d] - mx); tot += e[d]; }
        const float rinv = 1.f / tot;
        for (int d = 0; d < 4; d++) lw[(size_t)row * 4 + d] = e[d] * rinv;
    }
}

__global__ void decay_kernel(const float* __restrict__ td, float* __restrict__ dec)
{
    const int i = blockIdx.x * blockDim.x + threadIdx.x;
    if (i < DD * HH) dec[i] = expf(-expf(td[i]));
}

// attin(half) = sigmoid(r) * sum_d lw_d * (state*decay + k*v)   (v,k,r half)
__global__ __launch_bounds__(256) void attn_elem_kernel(
    const __half* __restrict__ v, const __half* __restrict__ k,
    const __half* __restrict__ rraw, const float* __restrict__ lw,
    const float* __restrict__ state, const float* __restrict__ dec,
    __half* __restrict__ attin)
{
    const size_t idx = (size_t)blockIdx.x * 256 + threadIdx.x;
    const int col = (int)(idx & (HH - 1));
    const int row = (int)(idx >> 11);
    const int b   = row >> 11;
    const float kv = __half2float(k[idx]) * __half2float(v[idx]);
    const float r  = 1.f / (1.f + __expf(-__half2float(rraw[idx])));
    const float* lwr = lw + (size_t)row * 4;
    float w = 0.f;
#pragma unroll
    for (int d = 0; d < DD; d++)
        w += lwr[d] * (state[((size_t)b * DD + d) * HH + col] * dec[d * HH + col] + kv);
    attin[idx] = __float2half(r * w);
}

// km(half) = h2*tmk + shift(h2)*(1-tmk)
__global__ __launch_bounds__(256) void km_kernel(
    const __half* __restrict__ h2, const float* __restrict__ cm,
    const float* __restrict__ tmk, __half* __restrict__ km)
{
    const size_t idx = (size_t)blockIdx.x * 256 + threadIdx.x;
    const int col = (int)(idx & (HH - 1));
    const int row = (int)(idx >> 11);
    const int t = row & (TT - 1);
    const int b = row >> 11;
    const float prev = (t == 0) ? cm[(size_t)b * HH + col] : __half2float(h2[idx - HH]);
    const float tk = tmk[col];
    km[idx] = __float2half(__half2float(h2[idx]) * tk + prev * (1.f - tk));
}

__global__ __launch_bounds__(256) void final_kernel(
    const float* __restrict__ x1, const float* __restrict__ val,
    const float* __restrict__ gate, float* __restrict__ out)
{
    const size_t idx = (size_t)blockIdx.x * 256 + threadIdx.x;
    const float g = 1.f / (1.f + __expf(-gate[idx]));
    out[idx] = x1[idx] + val[idx] * g;
}

// ---------------------------------------------------------------------------
extern "C" void kernel_launch(void* const* d_in, const int* in_sizes, int n_in,
                              void* d_out, int out_size)
{
    const float* x       = (const float*)d_in[0];
    const float* att_st  = (const float*)d_in[1];
    const float* cm_st   = (const float*)d_in[2];
    const float* ln1_s   = (const float*)d_in[3];
    const float* ln1_b   = (const float*)d_in[4];
    const float* ln2_s   = (const float*)d_in[5];
    const float* ln2_b   = (const float*)d_in[6];
    const float* td      = (const float*)d_in[7];
    const float* lvl_w   = (const float*)d_in[8];
    const float* lvl_b   = (const float*)d_in[9];
    const float* Wv      = (const float*)d_in[10];
    const float* Wk      = (const float*)d_in[11];
    const float* Wr      = (const float*)d_in[12];
    const float* Wo      = (const float*)d_in[13];
    const float* tmk     = (const float*)d_in[14];
    const float* Wkey    = (const float*)d_in[15];
    const float* Wval    = (const float*)d_in[16];
    const float* Wgate   = (const float*)d_in[17];
    float* out = (float*)d_out;

    __half *hh, *att, *kkh, *vh, *kh, *rh;
    float *val, *gat, *x1, *lw, *dec;
    __half *WvT, *WkT, *WrT, *WoT, *WkeyT, *WvalT, *WgateT;
    cudaGetSymbolAddress((void**)&hh,  g_hh);
    cudaGetSymbolAddress((void**)&att, g_att);
    cudaGetSymbolAddress((void**)&kkh, g_kkh);
    cudaGetSymbolAddress((void**)&vh,  g_vh);
    cudaGetSymbolAddress((void**)&kh,  g_kh);
    cudaGetSymbolAddress((void**)&rh,  g_rh);
    cudaGetSymbolAddress((void**)&val, g_val);
    cudaGetSymbolAddress((void**)&gat, g_gat);
    cudaGetSymbolAddress((void**)&x1,  g_x1);
    cudaGetSymbolAddress((void**)&lw,  g_lw);
    cudaGetSymbolAddress((void**)&dec, g_dec);
    cudaGetSymbolAddress((void**)&WvT,   g_WvT);
    cudaGetSymbolAddress((void**)&WkT,   g_WkT);
    cudaGetSymbolAddress((void**)&WrT,   g_WrT);
    cudaGetSymbolAddress((void**)&WoT,   g_WoT);
    cudaGetSymbolAddress((void**)&WkeyT, g_WkeyT);
    cudaGetSymbolAddress((void**)&WvalT, g_WvalT);
    cudaGetSymbolAddress((void**)&WgateT,g_WgateT);

    // opt-in dynamic smem for all GEMM instantiations
    cudaFuncSetAttribute(mma_gemm_kernel<0, __half>, cudaFuncAttributeMaxDynamicSharedMemorySize, GEMM_SMEM);
    cudaFuncSetAttribute(mma_gemm_kernel<0, float>,  cudaFuncAttributeMaxDynamicSharedMemorySize, GEMM_SMEM);
    cudaFuncSetAttribute(mma_gemm_kernel<1, float>,  cudaFuncAttributeMaxDynamicSharedMemorySize, GEMM_SMEM);
    cudaFuncSetAttribute(mma_gemm_kernel<2, __half>, cudaFuncAttributeMaxDynamicSharedMemorySize, GEMM_SMEM);

    const dim3 tb(32, 8);
    // weight transposes (fp32 -> fp16): out[N,K] = in[K,N]^T
    transpose_h_kernel<<<dim3(HH/32,  HH/32),  tb>>>(Wv,    WvT,    HH,  HH);
    transpose_h_kernel<<<dim3(HH/32,  HH/32),  tb>>>(Wk,    WkT,    HH,  HH);
    transpose_h_kernel<<<dim3(HH/32,  HH/32),  tb>>>(Wr,    WrT,    HH,  HH);
    transpose_h_kernel<<<dim3(HH/32,  HH/32),  tb>>>(Wo,    WoT,    HH,  HH);
    transpose_h_kernel<<<dim3(FFN/32, HH/32),  tb>>>(Wkey,  WkeyT,  HH,  FFN);
    transpose_h_kernel<<<dim3(HH/32,  FFN/32), tb>>>(Wval,  WvalT,  FFN, HH);
    transpose_h_kernel<<<dim3(HH/32,  FFN/32), tb>>>(Wgate, WgateT, FFN, HH);

    const dim3 gHH(HH / 128, MM / 128);     // N=2048: (16, 64)
    const dim3 gFF(FFN / 128, MM / 128);    // N=8192: (64, 64)
    const int ELEM_BLKS = (MM * HH) / 256;

    // --- attention half ---
    ln_kernel<<<MM, 256>>>(x, ln1_s, ln1_b, hh);
    mma_gemm_kernel<0, __half><<<gHH, 128, GEMM_SMEM>>>(hh, WvT, nullptr, vh, MM, HH, HH);
    mma_gemm_kernel<0, __half><<<gHH, 128, GEMM_SMEM>>>(hh, WkT, nullptr, kh, MM, HH, HH);
    mma_gemm_kernel<0, __half><<<gHH, 128, GEMM_SMEM>>>(hh, WrT, nullptr, rh, MM, HH, HH);
    lvl_kernel<<<MM, 256>>>(hh, lvl_w, lvl_b, lw);
    decay_kernel<<<(DD * HH + 255) / 256, 256>>>(td, dec);
    attn_elem_kernel<<<ELEM_BLKS, 256>>>(vh, kh, rh, lw, att_st, dec, att);
    mma_gemm_kernel<1, float><<<gHH, 128, GEMM_SMEM>>>(att, WoT, x, x1, MM, HH, HH);

    // --- channel-mix half ---
    ln_kernel<<<MM, 256>>>(x1, ln2_s, ln2_b, hh);                         // h2 -> hh
    km_kernel<<<ELEM_BLKS, 256>>>(hh, cm_st, tmk, att);                   // km -> att
    mma_gemm_kernel<2, __half><<<gFF, 128, GEMM_SMEM>>>(att, WkeyT, nullptr, kkh, MM, FFN, HH);
    mma_gemm_kernel<0, float><<<gHH, 128, GEMM_SMEM>>>(kkh, WvalT,  nullptr, val, MM, HH, FFN);
    mma_gemm_kernel<0, float><<<gHH, 128, GEMM_SMEM>>>(kkh, WgateT, nullptr, gat, MM, HH, FFN);
    final_kernel<<<ELEM_BLKS, 256>>>(x1, val, gat, out);
}

// round 14
// speedup vs baseline: 8.1432x; 1.0727x over previous
#include <cuda_runtime.h>
#include <cuda_fp16.h>
#include <cstdint>

// Problem constants
#define BB 4
#define TT 2048
#define HH 2048
#define DD 4
#define FFN 8192
#define MM (BB * TT)          // 8192 tokens

// Scratch (device globals: allocation-free per harness rules)
__device__ __half g_hh  [MM * HH];        // h (LN1) -> later h2 (LN2)
__device__ __half g_att [MM * HH];        // attin -> later km
__device__ __half g_kkh [MM * FFN];       // kk (half)
__device__ __half g_qkv [MM * 3 * HH];    // fused v|k|r outputs
__device__ float  g_vg  [MM * 2 * HH];    // fused val|gate outputs
__device__ float  g_x1  [MM * HH];        // x1
__device__ float  g_lw  [MM * DD];        // level softmax weights
__device__ float  g_dec [DD * HH];        // decay
// Transposed fp16 weights ([N,K] row-major for mma.sync row.col B operand)
__device__ __half g_WqkvT[3 * HH * HH];   // WvT | WkT | WrT (row blocks)
__device__ __half g_WoT  [HH * HH];
__device__ __half g_WkeyT[FFN * HH];
__device__ __half g_WvgT [2 * HH * FFN];  // WvalT | WgateT (row blocks)

// ---------------------------------------------------------------------------
__device__ __forceinline__ void mma_f16(float c[4], const uint32_t a[4], const uint32_t b[2]) {
    asm volatile(
        "mma.sync.aligned.m16n8k16.row.col.f32.f16.f16.f32 "
        "{%0,%1,%2,%3}, {%4,%5,%6,%7}, {%8,%9}, {%0,%1,%2,%3};"
        : "+f"(c[0]), "+f"(c[1]), "+f"(c[2]), "+f"(c[3])
        : "r"(a[0]), "r"(a[1]), "r"(a[2]), "r"(a[3]), "r"(b[0]), "r"(b[1]));
}

__device__ __forceinline__ void ldsm_x4(uint32_t& r0, uint32_t& r1, uint32_t& r2, uint32_t& r3,
                                        uint32_t addr) {
    asm volatile("ldmatrix.sync.aligned.m8n8.x4.shared.b16 {%0,%1,%2,%3}, [%4];"
                 : "=r"(r0), "=r"(r1), "=r"(r2), "=r"(r3) : "r"(addr));
}

__device__ __forceinline__ void cp_async16(uint32_t smem_addr, const void* gptr) {
    asm volatile("cp.async.ca.shared.global [%0], [%1], 16;" :: "r"(smem_addr), "l"(gptr));
}
__device__ __forceinline__ void cp_commit() {
    asm volatile("cp.async.commit_group;" ::: "memory");
}
__device__ __forceinline__ void cp_wait1() {
    asm volatile("cp.async.wait_group 1;" ::: "memory");
}

// ===========================================================================
// Tensor-core fp16 GEMM (fp32 accum): C[M,N] = A[M,K] @ Bt[N,K]^T
// Block tile 128x128, BK=32, 128 threads (4 warps = 2x2), warp tile 64x64.
// 3-stage cp.async pipeline (wait_group 1) + double-buffered ldmatrix frags.
// EPI: 0 plain, 1 +Res(float), 2 relu(.)^2.  OutT: float or __half.
// ===========================================================================
#define STAGE_BYTES 20480
#define GEMM_SMEM (3 * STAGE_BYTES)

template <int EPI, typename OutT>
__global__ __launch_bounds__(128, 2) void mma_gemm_kernel(
    const __half* __restrict__ A, const __half* __restrict__ Bt,
    const float* __restrict__ Res, OutT* __restrict__ C,
    int M, int N, int K)
{
    extern __shared__ uint32_t smem[];   // [3][256][20]; rows 0-127 A, 128-255 B
    const uint32_t smem_base = (uint32_t)__cvta_generic_to_shared(smem);

    const int tid = threadIdx.x;
    const int wid = tid >> 5, lane = tid & 31;
    const int wm = wid & 1, wn = wid >> 1;        // 2(m) x 2(n) warp grid
    const int group = lane >> 2, tg = lane & 3;   // mma fragment coords
    const int bm = blockIdx.y * 128, bn = blockIdx.x * 128;

    const __half* Arow = A  + (size_t)(bm + tid) * K;
    const __half* Brow = Bt + (size_t)(bn + tid) * K;
    const uint32_t sA = smem_base + tid * 80;
    const uint32_t sB = smem_base + (128 + tid) * 80;

    const int arow_l = wm * 64 + (lane & 7) + ((lane >> 3) & 1) * 8;
    const int acol_l = (lane >> 4) << 2;
    const int brow_l = wn * 64 + ((lane >> 4) << 3) + (lane & 7);
    const int bcol_l = ((lane >> 3) & 1) << 2;
    const uint32_t aoff = (uint32_t)(arow_l * 80 + acol_l * 4);
    const uint32_t boff = (uint32_t)((128 + brow_l) * 80 + bcol_l * 4);

    auto load_async = [&](int k0, int st) {
        const uint32_t off = (uint32_t)st * STAGE_BYTES;
#pragma unroll
        for (int cg = 0; cg < 4; cg++) {
            cp_async16(sA + off + cg * 16, Arow + k0 + cg * 8);
            cp_async16(sB + off + cg * 16, Brow + k0 + cg * 8);
        }
        cp_commit();
    };

    auto ldfrag = [&](int st, int kb, uint32_t af[4][4], uint32_t bf[8][2]) {
        const uint32_t sb = smem_base + (uint32_t)st * STAGE_BYTES + (uint32_t)kb;
#pragma unroll
        for (int mi = 0; mi < 4; mi++)
            ldsm_x4(af[mi][0], af[mi][1], af[mi][2], af[mi][3], sb + aoff + mi * 1280);
#pragma unroll
        for (int p = 0; p < 4; p++)
            ldsm_x4(bf[2 * p][0], bf[2 * p][1], bf[2 * p + 1][0], bf[2 * p + 1][1],
                    sb + boff + p * 1280);
    };

    float c[4][8][4];
#pragma unroll
    for (int mi = 0; mi < 4; mi++)
#pragma unroll
        for (int ni = 0; ni < 8; ni++)
#pragma unroll
            for (int j = 0; j < 4; j++) c[mi][ni][j] = 0.f;

    auto compute = [&](uint32_t af[4][4], uint32_t bf[8][2]) {
#pragma unroll
        for (int mi = 0; mi < 4; mi++)
#pragma unroll
            for (int ni = 0; ni < 8; ni++)
                mma_f16(c[mi][ni], af[mi], bf[ni]);
    };

    const int nt = K >> 5;
    load_async(0, 0);
    load_async(32, 1);
    cp_wait1();
    __syncthreads();

    uint32_t af0[4][4], bf0[8][2], af1[4][4], bf1[8][2];
    ldfrag(0, 0, af0, bf0);

    for (int t = 0; t < nt; ++t) {
        const int buf = t % 3;
        if (t + 2 < nt) load_async((t + 2) << 5, (t + 2) % 3);
        else cp_commit();
        ldfrag(buf, 32, af1, bf1);
        compute(af0, bf0);
        compute(af1, bf1);
        cp_wait1();
        __syncthreads();
        if (t + 1 < nt) ldfrag((t + 1) % 3, 0, af0, bf0);
    }

    // epilogue
#pragma unroll
    for (int mi = 0; mi < 4; mi++) {
        const int m0 = bm + wm * 64 + mi * 16 + group;
#pragma unroll
        for (int ni = 0; ni < 8; ni++) {
            const int n0 = bn + wn * 64 + ni * 8 + tg * 2;
            float2 lo = make_float2(c[mi][ni][0], c[mi][ni][1]);
            float2 hi = make_float2(c[mi][ni][2], c[mi][ni][3]);
            if (EPI == 1) {
                const float2 r0 = *(const float2*)(Res + (size_t)m0 * N + n0);
                const float2 r1 = *(const float2*)(Res + (size_t)(m0 + 8) * N + n0);
                lo.x += r0.x; lo.y += r0.y; hi.x += r1.x; hi.y += r1.y;
            }
            if (EPI == 2) {
                lo.x = fmaxf(lo.x, 0.f); lo.x *= lo.x;
                lo.y = fmaxf(lo.y, 0.f); lo.y *= lo.y;
                hi.x = fmaxf(hi.x, 0.f); hi.x *= hi.x;
                hi.y = fmaxf(hi.y, 0.f); hi.y *= hi.y;
            }
            if (sizeof(OutT) == 2) {
                *(__half2*)((__half*)C + (size_t)m0 * N + n0)       = __floats2half2_rn(lo.x, lo.y);
                *(__half2*)((__half*)C + (size_t)(m0 + 8) * N + n0) = __floats2half2_rn(hi.x, hi.y);
            } else {
                *(float2*)((float*)C + (size_t)m0 * N + n0)       = lo;
                *(float2*)((float*)C + (size_t)(m0 + 8) * N + n0) = hi;
            }
        }
    }
}

// ---------------------------------------------------------------------------
// Batched transpose + fp16 convert: in[z][R,C] fp32 -> out[z][C,R] fp16
// (up to 4 tensors of identical shape per launch; z selects)
// ---------------------------------------------------------------------------
__global__ __launch_bounds__(256) void transpose_h4_kernel(
    const float* i0, const float* i1, const float* i2, const float* i3,
    __half* o0, __half* o1, __half* o2, __half* o3, int R, int C)
{
    const int z = blockIdx.z;
    const float* in = (z == 0) ? i0 : (z == 1) ? i1 : (z == 2) ? i2 : i3;
    __half* out     = (z == 0) ? o0 : (z == 1) ? o1 : (z == 2) ? o2 : o3;
    __shared__ float tile[32][33];
    const int c0 = blockIdx.x * 32, r0 = blockIdx.y * 32;
    for (int i = threadIdx.y; i < 32; i += 8)
        tile[i][threadIdx.x] = in[(size_t)(r0 + i) * C + c0 + threadIdx.x];
    __syncthreads();
    for (int i = threadIdx.y; i < 32; i += 8)
        out[(size_t)(c0 + i) * R + r0 + threadIdx.x] = __float2half(tile[threadIdx.x][i]);
}

// ---------------------------------------------------------------------------
// LayerNorm -> fp16: one block per row of H=2048
// ---------------------------------------------------------------------------
__global__ __launch_bounds__(256) void ln_kernel(
    const float* __restrict__ x, const float* __restrict__ s,
    const float* __restrict__ bvec, __half* __restrict__ out)
{
    const int row = blockIdx.x;
    const float* xr = x + (size_t)row * HH;
    float sum = 0.f, sq = 0.f;
    for (int i = threadIdx.x; i < HH; i += 256) {
        float v = xr[i];
        sum += v;
        sq = fmaf(v, v, sq);
    }
    for (int o = 16; o; o >>= 1) {
        sum += __shfl_down_sync(0xffffffffu, sum, o);
        sq  += __shfl_down_sync(0xffffffffu, sq,  o);
    }
    __shared__ float s1[8], s2[8];
    const int lane = threadIdx.x & 31, w = threadIdx.x >> 5;
    if (!lane) { s1[w] = sum; s2[w] = sq; }
    __syncthreads();
    if (w == 0) {
        sum = (lane < 8) ? s1[lane] : 0.f;
        sq  = (lane < 8) ? s2[lane] : 0.f;
        for (int o = 4; o; o >>= 1) {
            sum += __shfl_down_sync(0xffffffffu, sum, o);
            sq  += __shfl_down_sync(0xffffffffu, sq,  o);
        }
        if (!lane) { s1[0] = sum; s2[0] = sq; }
    }
    __syncthreads();
    const float mean = s1[0] * (1.f / HH);
    const float var  = s2[0] * (1.f / HH) - mean * mean;
    const float inv  = rsqrtf(var + 1e-5f);
    __half* orow = out + (size_t)row * HH;
    for (int i = threadIdx.x; i < HH; i += 256)
        orow[i] = __float2half((xr[i] - mean) * inv * s[i] + bvec[i]);
}

// ---------------------------------------------------------------------------
// Level projection + softmax over D=4 (h fp16): one block per row
// ---------------------------------------------------------------------------
__global__ __launch_bounds__(256) void lvl_kernel(
    const __half* __restrict__ h, const float* __restrict__ W,
    const float* __restrict__ bias, float* __restrict__ lw)
{
    const int row = blockIdx.x;
    const __half* hr = h + (size_t)row * HH;
    float a0 = 0.f, a1 = 0.f, a2 = 0.f, a3 = 0.f;
    for (int i = threadIdx.x; i < HH; i += 256) {
        const float hv = __half2float(hr[i]);
        const float4 w = *(const float4*)(W + (size_t)i * 4);
        a0 = fmaf(hv, w.x, a0); a1 = fmaf(hv, w.y, a1);
        a2 = fmaf(hv, w.z, a2); a3 = fmaf(hv, w.w, a3);
    }
    for (int o = 16; o; o >>= 1) {
        a0 += __shfl_down_sync(0xffffffffu, a0, o);
        a1 += __shfl_down_sync(0xffffffffu, a1, o);
        a2 += __shfl_down_sync(0xffffffffu, a2, o);
        a3 += __shfl_down_sync(0xffffffffu, a3, o);
    }
    __shared__ float red[8][4];
    const int lane = threadIdx.x & 31, w = threadIdx.x >> 5;
    if (!lane) { red[w][0] = a0; red[w][1] = a1; red[w][2] = a2; red[w][3] = a3; }
    __syncthreads();
    if (threadIdx.x == 0) {
        float s[4];
        for (int d = 0; d < 4; d++) {
            s[d] = bias[d];
            for (int ww = 0; ww < 8; ww++) s[d] += red[ww][d];
        }
        float mx = fmaxf(fmaxf(s[0], s[1]), fmaxf(s[2], s[3]));
        float e[4], tot = 0.f;
        for (int d = 0; d < 4; d++) { e[d] = expf(s[d] - mx); tot += e[d]; }
        const float rinv = 1.f / tot;
        for (int d = 0; d < 4; d++) lw[(size_t)row * 4 + d] = e[d] * rinv;
    }
}

__global__ void decay_kernel(const float* __restrict__ td, float* __restrict__ dec)
{
    const int i = blockIdx.x * blockDim.x + threadIdx.x;
    if (i < DD * HH) dec[i] = expf(-expf(td[i]));
}

// attin(half) = sigmoid(r) * sum_d lw_d * (state*decay + k*v); qkv strided v|k|r
__global__ __launch_bounds__(256) void attn_elem_kernel(
    const __half* __restrict__ qkv, const float* __restrict__ lw,
    const float* __restrict__ state, const float* __restrict__ dec,
    __half* __restrict__ attin)
{
    const size_t idx = (size_t)blockIdx.x * 256 + threadIdx.x;
    const int col = (int)(idx & (HH - 1));
    const int row = (int)(idx >> 11);
    const int b   = row >> 11;
    const size_t base = (size_t)row * (3 * HH) + col;
    const float v  = __half2float(qkv[base]);
    const float k  = __half2float(qkv[base + HH]);
    const float rr = __half2float(qkv[base + 2 * HH]);
    const float kv = k * v;
    const float r  = 1.f / (1.f + __expf(-rr));
    const float* lwr = lw + (size_t)row * 4;
    float w = 0.f;
#pragma unroll
    for (int d = 0; d < DD; d++)
        w += lwr[d] * (state[((size_t)b * DD + d) * HH + col] * dec[d * HH + col] + kv);
    attin[idx] = __float2half(r * w);
}

// km(half) = h2*tmk + shift(h2)*(1-tmk)
__global__ __launch_bounds__(256) void km_kernel(
    const __half* __restrict__ h2, const float* __restrict__ cm,
    const float* __restrict__ tmk, __half* __restrict__ km)
{
    const size_t idx = (size_t)blockIdx.x * 256 + threadIdx.x;
    const int col = (int)(idx & (HH - 1));
    const int row = (int)(idx >> 11);
    const int t = row & (TT - 1);
    const int b = row >> 11;
    const float prev = (t == 0) ? cm[(size_t)b * HH + col] : __half2float(h2[idx - HH]);
    const float tk = tmk[col];
    km[idx] = __float2half(__half2float(h2[idx]) * tk + prev * (1.f - tk));
}

// out = x1 + val * sigmoid(gate); vg strided val|gate
__global__ __launch_bounds__(256) void final_kernel(
    const float* __restrict__ x1, const float* __restrict__ vg,
    float* __restrict__ out)
{
    const size_t idx = (size_t)blockIdx.x * 256 + threadIdx.x;
    const int col = (int)(idx & (HH - 1));
    const int row = (int)(idx >> 11);
    const size_t base = (size_t)row * (2 * HH) + col;
    const float g = 1.f / (1.f + __expf(-vg[base + HH]));
    out[idx] = x1[idx] + vg[base] * g;
}

// ---------------------------------------------------------------------------
extern "C" void kernel_launch(void* const* d_in, const int* in_sizes, int n_in,
                              void* d_out, int out_size)
{
    const float* x       = (const float*)d_in[0];
    const float* att_st  = (const float*)d_in[1];
    const float* cm_st   = (const float*)d_in[2];
    const float* ln1_s   = (const float*)d_in[3];
    const float* ln1_b   = (const float*)d_in[4];
    const float* ln2_s   = (const float*)d_in[5];
    const float* ln2_b   = (const float*)d_in[6];
    const float* td      = (const float*)d_in[7];
    const float* lvl_w   = (const float*)d_in[8];
    const float* lvl_b   = (const float*)d_in[9];
    const float* Wv      = (const float*)d_in[10];
    const float* Wk      = (const float*)d_in[11];
    const float* Wr      = (const float*)d_in[12];
    const float* Wo      = (const float*)d_in[13];
    const float* tmk     = (const float*)d_in[14];
    const float* Wkey    = (const float*)d_in[15];
    const float* Wval    = (const float*)d_in[16];
    const float* Wgate   = (const float*)d_in[17];
    float* out = (float*)d_out;

    __half *hh, *att, *kkh, *qkv;
    float *vg, *x1, *lw, *dec;
    __half *WqkvT, *WoT, *WkeyT, *WvgT;
    cudaGetSymbolAddress((void**)&hh,   g_hh);
    cudaGetSymbolAddress((void**)&att,  g_att);
    cudaGetSymbolAddress((void**)&kkh,  g_kkh);
    cudaGetSymbolAddress((void**)&qkv,  g_qkv);
    cudaGetSymbolAddress((void**)&vg,   g_vg);
    cudaGetSymbolAddress((void**)&x1,   g_x1);
    cudaGetSymbolAddress((void**)&lw,   g_lw);
    cudaGetSymbolAddress((void**)&dec,  g_dec);
    cudaGetSymbolAddress((void**)&WqkvT, g_WqkvT);
    cudaGetSymbolAddress((void**)&WoT,   g_WoT);
    cudaGetSymbolAddress((void**)&WkeyT, g_WkeyT);
    cudaGetSymbolAddress((void**)&WvgT,  g_WvgT);

    // opt-in dynamic smem for all GEMM instantiations
    cudaFuncSetAttribute(mma_gemm_kernel<0, __half>, cudaFuncAttributeMaxDynamicSharedMemorySize, GEMM_SMEM);
    cudaFuncSetAttribute(mma_gemm_kernel<0, float>,  cudaFuncAttributeMaxDynamicSharedMemorySize, GEMM_SMEM);
    cudaFuncSetAttribute(mma_gemm_kernel<1, float>,  cudaFuncAttributeMaxDynamicSharedMemorySize, GEMM_SMEM);
    cudaFuncSetAttribute(mma_gemm_kernel<2, __half>, cudaFuncAttributeMaxDynamicSharedMemorySize, GEMM_SMEM);

    const dim3 tb(32, 8);
    // Batched weight transposes (fp32 -> fp16), out[N,K] = in[K,N]^T:
    // 4x [HH,HH]: Wv,Wk,Wr -> WqkvT row blocks; Wo -> WoT
    transpose_h4_kernel<<<dim3(HH/32, HH/32, 4), tb>>>(
        Wv, Wk, Wr, Wo,
        WqkvT, WqkvT + (size_t)HH * HH, WqkvT + (size_t)2 * HH * HH, WoT,
        HH, HH);
    // 2x [FFN,HH]: Wval,Wgate -> WvgT row blocks
    transpose_h4_kernel<<<dim3(HH/32, FFN/32, 2), tb>>>(
        Wval, Wgate, Wval, Wgate,
        WvgT, WvgT + (size_t)HH * FFN, WvgT, WvgT + (size_t)HH * FFN,
        FFN, HH);
    // 1x [HH,FFN]: Wkey -> WkeyT
    transpose_h4_kernel<<<dim3(FFN/32, HH/32, 1), tb>>>(
        Wkey, Wkey, Wkey, Wkey, WkeyT, WkeyT, WkeyT, WkeyT, HH, FFN);

    const dim3 gQKV(3 * HH / 128, MM / 128);   // (48, 64)
    const dim3 gHHd(HH / 128, MM / 128);       // (16, 64)
    const dim3 gFF (FFN / 128, MM / 128);      // (64, 64)
    const dim3 gVG (2 * HH / 128, MM / 128);   // (32, 64)
    const int ELEM_BLKS = (MM * HH) / 256;

    // --- attention half ---
    ln_kernel<<<MM, 256>>>(x, ln1_s, ln1_b, hh);
    mma_gemm_kernel<0, __half><<<gQKV, 128, GEMM_SMEM>>>(hh, WqkvT, nullptr, qkv, MM, 3 * HH, HH);
    lvl_kernel<<<MM, 256>>>(hh, lvl_w, lvl_b, lw);
    decay_kernel<<<(DD * HH + 255) / 256, 256>>>(td, dec);
    attn_elem_kernel<<<ELEM_BLKS, 256>>>(qkv, lw, att_st, dec, att);
    mma_gemm_kernel<1, float><<<gHHd, 128, GEMM_SMEM>>>(att, WoT, x, x1, MM, HH, HH);

    // --- channel-mix half ---
    ln_kernel<<<MM, 256>>>(x1, ln2_s, ln2_b, hh);                          // h2 -> hh
    km_kernel<<<ELEM_BLKS, 256>>>(hh, cm_st, tmk, att);                    // km -> att
    mma_gemm_kernel<2, __half><<<gFF, 128, GEMM_SMEM>>>(att, WkeyT, nullptr, kkh, MM, FFN, HH);
    mma_gemm_kernel<0, float><<<gVG, 128, GEMM_SMEM>>>(kkh, WvgT, nullptr, vg, MM, 2 * HH, FFN);
    final_kernel<<<ELEM_BLKS, 256>>>(x1, vg, out);
}